// round 10
// baseline (speedup 1.0000x reference)
#include <cuda_runtime.h>
#include <cuda_bf16.h>
#include <cstdint>
#include <math.h>

// Problem constants
#define BATCH   2
#define SEQ     2048
#define HID     1024
#define HEADS   16
#define DH      64
#define MTOT    (BATCH * SEQ)          // 4096

// ---------------------------------------------------------------------------
// Scratch (device globals — no allocation allowed)
// ---------------------------------------------------------------------------
__device__ float g_qkv[(size_t)3 * BATCH * HEADS * SEQ * DH];        // fp32 [c,b,h,s,d]
__device__ __nv_bfloat16 g_attn_h[(size_t)MTOT * HID];
__device__ __nv_bfloat16 g_attn_l[(size_t)MTOT * HID];
__device__ __nv_bfloat16 g_x_h[(size_t)MTOT * HID];
__device__ __nv_bfloat16 g_x_l[(size_t)MTOT * HID];
__device__ __nv_bfloat16 g_wq_h[(size_t)3 * HID * HID];   // [3072][1024] = W_qkv^T
__device__ __nv_bfloat16 g_wq_l[(size_t)3 * HID * HID];
__device__ __nv_bfloat16 g_wo_h[(size_t)HID * HID];       // [1024][1024] = W_out^T
__device__ __nv_bfloat16 g_wo_l[(size_t)HID * HID];

// ---------------------------------------------------------------------------
// PTX helpers (baseline sm_103 ISA only: ldmatrix + mma.sync, NO tcgen05)
// ---------------------------------------------------------------------------
__device__ __forceinline__ uint32_t smem_u32(const void* p) {
    uint32_t a;
    asm("{ .reg .u64 t; cvta.to.shared.u64 t, %1; cvt.u32.u64 %0, t; }" : "=r"(a) : "l"(p));
    return a;
}
#define SWZ(o) ((o) ^ (((o) >> 3) & 0x70))
#define STS128(addr, v) \
    asm volatile("st.shared.v4.b32 [%0], {%1,%2,%3,%4};" \
                 :: "r"(addr), "r"(v.x), "r"(v.y), "r"(v.z), "r"(v.w) : "memory")

#define LDSM_X4(r, addr) \
    asm volatile("ldmatrix.sync.aligned.m8n8.x4.shared.b16 {%0,%1,%2,%3}, [%4];" \
        : "=r"((r)[0]), "=r"((r)[1]), "=r"((r)[2]), "=r"((r)[3]) : "r"(addr))
#define LDSM_X2(r, addr) \
    asm volatile("ldmatrix.sync.aligned.m8n8.x2.shared.b16 {%0,%1}, [%2];" \
        : "=r"((r)[0]), "=r"((r)[1]) : "r"(addr))
#define MMA16816(d, a, b) \
    asm volatile("mma.sync.aligned.m16n8k16.row.col.f32.bf16.bf16.f32 " \
        "{%0,%1,%2,%3}, {%4,%5,%6,%7}, {%8,%9}, {%0,%1,%2,%3};" \
        : "+f"((d)[0]), "+f"((d)[1]), "+f"((d)[2]), "+f"((d)[3]) \
        : "r"((a)[0]), "r"((a)[1]), "r"((a)[2]), "r"((a)[3]), \
          "r"((b)[0]), "r"((b)[1]))

// ---------------------------------------------------------------------------
// Prep kernels: fp32 -> bf16 hi/lo split (and weight transpose)
// ---------------------------------------------------------------------------
__global__ __launch_bounds__(256) void split_f32(
    const float* __restrict__ s, __nv_bfloat16* __restrict__ hi,
    __nv_bfloat16* __restrict__ lo, int n4)
{
    int i = blockIdx.x * 256 + threadIdx.x;
    if (i >= n4) return;
    float4 v = ((const float4*)s)[i];
    union { __nv_bfloat16 b[4]; uint2 u; } ph, pl;
    float f[4] = {v.x, v.y, v.z, v.w};
#pragma unroll
    for (int j = 0; j < 4; j++) {
        __nv_bfloat16 h = __float2bfloat16(f[j]);
        ph.b[j] = h;
        pl.b[j] = __float2bfloat16(f[j] - __bfloat162float(h));
    }
    ((uint2*)hi)[i] = ph.u;
    ((uint2*)lo)[i] = pl.u;
}

// W[K][N] -> Th/Tl[N][K]  (transpose + split)
__global__ void transpose_split(const float* __restrict__ W,
                                __nv_bfloat16* __restrict__ Th,
                                __nv_bfloat16* __restrict__ Tl, int K, int N)
{
    __shared__ float t[32][33];
    const int k0 = blockIdx.y * 32, n0 = blockIdx.x * 32;
    const int tx = threadIdx.x, ty = threadIdx.y;
    for (int j = ty; j < 32; j += 8)
        t[j][tx] = W[(size_t)(k0 + j) * N + n0 + tx];
    __syncthreads();
    for (int j = ty; j < 32; j += 8) {
        float v = t[tx][j];
        __nv_bfloat16 h = __float2bfloat16(v);
        Th[(size_t)(n0 + j) * K + k0 + tx] = h;
        Tl[(size_t)(n0 + j) * K + k0 + tx] = __float2bfloat16(v - __bfloat162float(h));
    }
}

// ---------------------------------------------------------------------------
// mma.sync GEMM with bf16 hi/lo split (3 passes), fp32 accumulate.
// C[M,N] = A[M,K] @ B[N,K]^T + bias[N]
// 128x128 CTA tile, K-chunk 64, 256 threads = 8 warps (2M x 4N, 64x32 each).
// mode 0: plain write to C.  mode 1: scatter into g_qkv ([3,B,H,S,Dh]).
// ---------------------------------------------------------------------------
#define GT_SMEM (4 * 16384 + 1024)

__global__ __launch_bounds__(256, 2) void gemm_tc(
    const __nv_bfloat16* __restrict__ Ah, const __nv_bfloat16* __restrict__ Al,
    const __nv_bfloat16* __restrict__ Bh, const __nv_bfloat16* __restrict__ Bl,
    const float* __restrict__ bias, float* __restrict__ C,
    int M, int N, int K, int mode)
{
    extern __shared__ char smraw[];
    const uint32_t smem0 = smem_u32(smraw);
    const uint32_t tile  = (smem0 + 1023u) & ~1023u;   // 1024-aligned tiles
    const uint32_t sA_h = tile, sA_l = tile + 16384;
    const uint32_t sB_h = tile + 32768, sB_l = tile + 49152;

    const int tid  = threadIdx.x;
    const int wid  = tid >> 5, lane = tid & 31;
    const int wm   = wid & 1, wn = wid >> 1;        // 2 x 4 warp grid
    const int bm   = blockIdx.y << 7, bn = blockIdx.x << 7;

    // per-thread fragment base offsets (bytes within a 128x64-bf16 SW128 tile)
    uint32_t a_base[4], b_base[4];
#pragma unroll
    for (int mi = 0; mi < 4; mi++) {
        const int rowA = wm * 64 + mi * 16 + (lane & 15);
        a_base[mi] = (uint32_t)rowA * 128 + (((uint32_t)lane >> 4) << 4);
    }
    const int l15 = lane & 15;
#pragma unroll
    for (int ni = 0; ni < 4; ni++) {
        const int rowB = wn * 32 + ni * 8 + (l15 & 7);
        b_base[ni] = (uint32_t)rowB * 128 + (((uint32_t)l15 >> 3) << 4);
    }

    float d[4][4][4];
#pragma unroll
    for (int mi = 0; mi < 4; mi++)
#pragma unroll
        for (int ni = 0; ni < 4; ni++)
#pragma unroll
            for (int k = 0; k < 4; k++) d[mi][ni][k] = 0.f;

    for (int kc = 0; kc < K; kc += 64) {
        __syncthreads();   // previous chunk's readers done
        // ---- stage 4 tiles (128 rows x 64 bf16 = 128B/row, SW128) ----
#pragma unroll
        for (int i = 0; i < 4; i++) {
            const int idx = tid + (i << 8);        // 0..1023
            const int r = idx >> 3, c = idx & 7;   // row, 16B-chunk
            const uint32_t so = SWZ((uint32_t)r * 128 + (uint32_t)c * 16);
            const size_t gA = (size_t)(bm + r) * K + kc + c * 8;
            const size_t gB = (size_t)(bn + r) * K + kc + c * 8;
            uint4 v;
            v = *(const uint4*)(Ah + gA); STS128(sA_h + so, v);
            v = *(const uint4*)(Al + gA); STS128(sA_l + so, v);
            v = *(const uint4*)(Bh + gB); STS128(sB_h + so, v);
            v = *(const uint4*)(Bl + gB); STS128(sB_l + so, v);
        }
        __syncthreads();

        // ---- compute: 4 k-steps of 16, 3 split passes each ----
#pragma unroll
        for (int ks = 0; ks < 4; ks++) {
            const uint32_t kb = (uint32_t)ks << 5;   // k-step byte offset
            uint32_t fAh[4][4], fAl[4][4], fBh[4][2], fBl[4][2];
#pragma unroll
            for (int mi = 0; mi < 4; mi++) {
                LDSM_X4(fAh[mi], sA_h + SWZ(a_base[mi] + kb));
                LDSM_X4(fAl[mi], sA_l + SWZ(a_base[mi] + kb));
            }
#pragma unroll
            for (int ni = 0; ni < 4; ni++) {
                LDSM_X2(fBh[ni], sB_h + SWZ(b_base[ni] + kb));
                LDSM_X2(fBl[ni], sB_l + SWZ(b_base[ni] + kb));
            }
#pragma unroll
            for (int mi = 0; mi < 4; mi++)
#pragma unroll
                for (int ni = 0; ni < 4; ni++) {
                    MMA16816(d[mi][ni], fAh[mi], fBh[ni]);
                    MMA16816(d[mi][ni], fAh[mi], fBl[ni]);
                    MMA16816(d[mi][ni], fAl[mi], fBh[ni]);
                }
        }
    }

    // ---- epilogue: direct float2 stores with bias ----
    const int q = lane >> 2;           // 0..7 (row within 8)
    const int cpair = (lane & 3) << 1; // 0,2,4,6
#pragma unroll
    for (int ni = 0; ni < 4; ni++) {
        const int n = bn + wn * 32 + ni * 8 + cpair;
        const float2 bs = *(const float2*)(bias + n);
#pragma unroll
        for (int mi = 0; mi < 4; mi++) {
#pragma unroll
            for (int hh = 0; hh < 2; hh++) {
                const int m = bm + wm * 64 + mi * 16 + q + hh * 8;
                float2 v;
                v.x = d[mi][ni][hh * 2 + 0] + bs.x;
                v.y = d[mi][ni][hh * 2 + 1] + bs.y;
                if (mode == 1) {
                    const int cc = n >> 10, hd = (n >> 6) & 15, dd = n & 63;
                    const int bb = m >> 11, ss = m & 2047;
                    *(float2*)(g_qkv +
                        (((size_t)((cc * 2 + bb) * 16 + hd) * 2048 + ss) * 64 + dd)) = v;
                } else {
                    *(float2*)(C + (size_t)m * N + n) = v;
                }
            }
        }
    }
}

// ---------------------------------------------------------------------------
// Flash attention (fp32 SIMT, unchanged proven math) — epilogue emits
// bf16 hi/lo directly for the output projection.
// ---------------------------------------------------------------------------
#define QS_F   (64 * 64)
#define KS_F   (64 * 65)
#define VS_F   (64 * 64)
#define PS_F   (64 * 64)
#define ATTN_SMEM ((QS_F + KS_F + VS_F + PS_F) * 4)   // 65792 bytes

__global__ __launch_bounds__(256) void attn_kernel()
{
    extern __shared__ float sm[];
    float* Qs = sm;
    float* Ks = sm + QS_F;
    float* Vs = sm + QS_F + KS_F;
    float* Ps = sm + QS_F + KS_F + VS_F;

    const int tid = threadIdx.x;
    const int tx = tid & 15;
    const int ty = tid >> 4;
    const int bh = blockIdx.y;
    const int b = bh >> 4;
    const int h = bh & 15;
    const int q0 = blockIdx.x << 6;

    const float* Qp = g_qkv + (size_t)((0 * BATCH + b) * HEADS + h) * (SEQ * DH);
    const float* Kp = g_qkv + (size_t)((1 * BATCH + b) * HEADS + h) * (SEQ * DH);
    const float* Vp = g_qkv + (size_t)((2 * BATCH + b) * HEADS + h) * (SEQ * DH);

    for (int i = tid; i < 1024; i += 256) {
        const int r = i >> 4;
        const int c4 = (i & 15) << 2;
        float4 v = *(const float4*)(Qp + (size_t)(q0 + r) * DH + c4);
        float* q = Qs + r * 64 + c4;
        q[0] = v.x * 0.125f; q[1] = v.y * 0.125f;
        q[2] = v.z * 0.125f; q[3] = v.w * 0.125f;
    }

    float o[4][4];
    float m_i[4], l_i[4];
#pragma unroll
    for (int i = 0; i < 4; i++) {
        m_i[i] = -3.0e38f; l_i[i] = 0.f;
#pragma unroll
        for (int j = 0; j < 4; j++) o[i][j] = 0.f;
    }

    for (int kt = 0; kt < SEQ / 64; ++kt) {
        __syncthreads();

        const float* kp = Kp + (size_t)(kt << 6) * DH;
        const float* vp = Vp + (size_t)(kt << 6) * DH;
        for (int i = tid; i < 1024; i += 256) {
            const int r = i >> 4;
            const int c4 = (i & 15) << 2;
            float4 kv = *(const float4*)(kp + r * DH + c4);
            float* kd = Ks + r * 65 + c4;
            kd[0] = kv.x; kd[1] = kv.y; kd[2] = kv.z; kd[3] = kv.w;
            float4 vv = *(const float4*)(vp + r * DH + c4);
            float* vd = Vs + r * 64 + c4;
            vd[0] = vv.x; vd[1] = vv.y; vd[2] = vv.z; vd[3] = vv.w;
        }
        __syncthreads();

        float s[4][4];
#pragma unroll
        for (int i = 0; i < 4; i++)
#pragma unroll
            for (int j = 0; j < 4; j++) s[i][j] = 0.f;

        const float* qb = Qs + (ty * 4) * 64;
        const float* kb = Ks + (tx * 4) * 65;
#pragma unroll 8
        for (int k = 0; k < 64; ++k) {
            float a0 = qb[0 * 64 + k], a1 = qb[1 * 64 + k];
            float a2 = qb[2 * 64 + k], a3 = qb[3 * 64 + k];
            float c0 = kb[0 * 65 + k], c1 = kb[1 * 65 + k];
            float c2 = kb[2 * 65 + k], c3 = kb[3 * 65 + k];
            s[0][0] = fmaf(a0, c0, s[0][0]); s[0][1] = fmaf(a0, c1, s[0][1]);
            s[0][2] = fmaf(a0, c2, s[0][2]); s[0][3] = fmaf(a0, c3, s[0][3]);
            s[1][0] = fmaf(a1, c0, s[1][0]); s[1][1] = fmaf(a1, c1, s[1][1]);
            s[1][2] = fmaf(a1, c2, s[1][2]); s[1][3] = fmaf(a1, c3, s[1][3]);
            s[2][0] = fmaf(a2, c0, s[2][0]); s[2][1] = fmaf(a2, c1, s[2][1]);
            s[2][2] = fmaf(a2, c2, s[2][2]); s[2][3] = fmaf(a2, c3, s[2][3]);
            s[3][0] = fmaf(a3, c0, s[3][0]); s[3][1] = fmaf(a3, c1, s[3][1]);
            s[3][2] = fmaf(a3, c2, s[3][2]); s[3][3] = fmaf(a3, c3, s[3][3]);
        }

#pragma unroll
        for (int i = 0; i < 4; i++) {
            float rmax = fmaxf(fmaxf(s[i][0], s[i][1]), fmaxf(s[i][2], s[i][3]));
#pragma unroll
            for (int off = 1; off < 16; off <<= 1)
                rmax = fmaxf(rmax, __shfl_xor_sync(0xffffffffu, rmax, off));
            const float mnew = fmaxf(m_i[i], rmax);
            const float alpha = __expf(m_i[i] - mnew);
            float rsum = 0.f;
#pragma unroll
            for (int j = 0; j < 4; j++) {
                float p = __expf(s[i][j] - mnew);
                s[i][j] = p;
                rsum += p;
            }
#pragma unroll
            for (int off = 1; off < 16; off <<= 1)
                rsum += __shfl_xor_sync(0xffffffffu, rsum, off);
            l_i[i] = l_i[i] * alpha + rsum;
            m_i[i] = mnew;
#pragma unroll
            for (int j = 0; j < 4; j++) o[i][j] *= alpha;
        }

#pragma unroll
        for (int i = 0; i < 4; i++)
#pragma unroll
            for (int j = 0; j < 4; j++)
                Ps[(ty * 4 + i) * 64 + tx * 4 + j] = s[i][j];
        __syncthreads();

        const float* pb = Ps + (ty * 4) * 64;
        const float* vb = Vs + tx * 4;
#pragma unroll 8
        for (int t = 0; t < 64; ++t) {
            float p0 = pb[0 * 64 + t], p1 = pb[1 * 64 + t];
            float p2 = pb[2 * 64 + t], p3 = pb[3 * 64 + t];
            float v0 = vb[t * 64 + 0], v1 = vb[t * 64 + 1];
            float v2 = vb[t * 64 + 2], v3 = vb[t * 64 + 3];
            o[0][0] = fmaf(p0, v0, o[0][0]); o[0][1] = fmaf(p0, v1, o[0][1]);
            o[0][2] = fmaf(p0, v2, o[0][2]); o[0][3] = fmaf(p0, v3, o[0][3]);
            o[1][0] = fmaf(p1, v0, o[1][0]); o[1][1] = fmaf(p1, v1, o[1][1]);
            o[1][2] = fmaf(p1, v2, o[1][2]); o[1][3] = fmaf(p1, v3, o[1][3]);
            o[2][0] = fmaf(p2, v0, o[2][0]); o[2][1] = fmaf(p2, v1, o[2][1]);
            o[2][2] = fmaf(p2, v2, o[2][2]); o[2][3] = fmaf(p2, v3, o[2][3]);
            o[3][0] = fmaf(p3, v0, o[3][0]); o[3][1] = fmaf(p3, v1, o[3][1]);
            o[3][2] = fmaf(p3, v2, o[3][2]); o[3][3] = fmaf(p3, v3, o[3][3]);
        }
    }

    // finalize + bf16 hi/lo write [b, s, h*64+d]
#pragma unroll
    for (int i = 0; i < 4; i++) {
        const float inv = 1.0f / l_i[i];
        const int row = q0 + ty * 4 + i;
        const size_t base = ((size_t)b * SEQ + row) * HID + h * DH + tx * 4;
#pragma unroll
        for (int j = 0; j < 4; j++) {
            const float v = o[i][j] * inv;
            const __nv_bfloat16 hb = __float2bfloat16(v);
            g_attn_h[base + j] = hb;
            g_attn_l[base + j] = __float2bfloat16(v - __bfloat162float(hb));
        }
    }
}

// ---------------------------------------------------------------------------
extern "C" void kernel_launch(void* const* d_in, const int* in_sizes, int n_in,
                              void* d_out, int out_size)
{
    const float* x    = (const float*)d_in[0];
    const float* Wqkv = (const float*)d_in[1];
    const float* bqkv = (const float*)d_in[2];
    const float* Wout = (const float*)d_in[3];
    const float* bout = (const float*)d_in[4];
    float* out = (float*)d_out;

    cudaFuncSetAttribute(attn_kernel,
                         cudaFuncAttributeMaxDynamicSharedMemorySize, ATTN_SMEM);
    cudaFuncSetAttribute(gemm_tc,
                         cudaFuncAttributeMaxDynamicSharedMemorySize, GT_SMEM);

    __nv_bfloat16 *xh, *xl, *wqh, *wql, *woh, *wol, *ath, *atl;
    cudaGetSymbolAddress((void**)&xh,  g_x_h);
    cudaGetSymbolAddress((void**)&xl,  g_x_l);
    cudaGetSymbolAddress((void**)&wqh, g_wq_h);
    cudaGetSymbolAddress((void**)&wql, g_wq_l);
    cudaGetSymbolAddress((void**)&woh, g_wo_h);
    cudaGetSymbolAddress((void**)&wol, g_wo_l);
    cudaGetSymbolAddress((void**)&ath, g_attn_h);
    cudaGetSymbolAddress((void**)&atl, g_attn_l);

    // 0) prep: split x; transpose+split weights
    split_f32<<<(MTOT * HID / 4 + 255) / 256, 256>>>(x, xh, xl, MTOT * HID / 4);
    transpose_split<<<dim3(3 * HID / 32, HID / 32), dim3(32, 8)>>>(Wqkv, wqh, wql, HID, 3 * HID);
    transpose_split<<<dim3(HID / 32, HID / 32), dim3(32, 8)>>>(Wout, woh, wol, HID, HID);

    // 1) QKV projection (mma.sync bf16-split) + bias -> g_qkv [3,B,H,S,Dh] fp32
    gemm_tc<<<dim3(3 * HID / 128, MTOT / 128), 256, GT_SMEM>>>(
        xh, xl, wqh, wql, bqkv, nullptr, MTOT, 3 * HID, HID, 1);

    // 2) Attention -> g_attn_h/l [B,S,H*Dh] (bf16 split)
    attn_kernel<<<dim3(SEQ / 64, BATCH * HEADS), 256, ATTN_SMEM>>>();

    // 3) Output projection (mma.sync bf16-split) + bias -> out
    gemm_tc<<<dim3(HID / 128, MTOT / 128), 256, GT_SMEM>>>(
        ath, atl, woh, wol, bout, out, MTOT, HID, HID, 0);
}

// round 11
// speedup vs baseline: 2.0252x; 2.0252x over previous
#include <cuda_runtime.h>
#include <cuda_bf16.h>
#include <cstdint>
#include <math.h>

// Problem constants
#define BATCH   2
#define SEQ     2048
#define HID     1024
#define HEADS   16
#define DH      64
#define MTOT    (BATCH * SEQ)          // 4096
#define NBH     (BATCH * HEADS)        // 32

// ---------------------------------------------------------------------------
// Scratch (device globals — no allocation allowed)
// ---------------------------------------------------------------------------
#define QKV_ELEMS ((size_t)NBH * SEQ * DH)          // 4.19M per tensor
__device__ __nv_bfloat16 g_q_h[QKV_ELEMS], g_q_l[QKV_ELEMS];
__device__ __nv_bfloat16 g_k_h[QKV_ELEMS], g_k_l[QKV_ELEMS];
__device__ __nv_bfloat16 g_v_h[QKV_ELEMS], g_v_l[QKV_ELEMS];
__device__ __nv_bfloat16 g_attn_h[(size_t)MTOT * HID];
__device__ __nv_bfloat16 g_attn_l[(size_t)MTOT * HID];
__device__ __nv_bfloat16 g_x_h[(size_t)MTOT * HID];
__device__ __nv_bfloat16 g_x_l[(size_t)MTOT * HID];
__device__ __nv_bfloat16 g_wq_h[(size_t)3 * HID * HID];   // [3072][1024] = W_qkv^T
__device__ __nv_bfloat16 g_wq_l[(size_t)3 * HID * HID];
__device__ __nv_bfloat16 g_wo_h[(size_t)HID * HID];       // [1024][1024] = W_out^T
__device__ __nv_bfloat16 g_wo_l[(size_t)HID * HID];

// ---------------------------------------------------------------------------
// PTX helpers (baseline sm_103 ISA: ldmatrix + mma.sync + cp.async)
// ---------------------------------------------------------------------------
__device__ __forceinline__ uint32_t smem_u32(const void* p) {
    uint32_t a;
    asm("{ .reg .u64 t; cvta.to.shared.u64 t, %1; cvt.u32.u64 %0, t; }" : "=r"(a) : "l"(p));
    return a;
}
#define SWZ(o) ((o) ^ (((o) >> 3) & 0x70))
#define STS128(addr, v) \
    asm volatile("st.shared.v4.b32 [%0], {%1,%2,%3,%4};" \
                 :: "r"(addr), "r"(v.x), "r"(v.y), "r"(v.z), "r"(v.w) : "memory")

#define LDSM_X4(r, addr) \
    asm volatile("ldmatrix.sync.aligned.m8n8.x4.shared.b16 {%0,%1,%2,%3}, [%4];" \
        : "=r"((r)[0]), "=r"((r)[1]), "=r"((r)[2]), "=r"((r)[3]) : "r"(addr))
#define LDSM_X4T(r, addr) \
    asm volatile("ldmatrix.sync.aligned.m8n8.x4.trans.shared.b16 {%0,%1,%2,%3}, [%4];" \
        : "=r"((r)[0]), "=r"((r)[1]), "=r"((r)[2]), "=r"((r)[3]) : "r"(addr))
#define LDSM_X2(r, addr) \
    asm volatile("ldmatrix.sync.aligned.m8n8.x2.shared.b16 {%0,%1}, [%2];" \
        : "=r"((r)[0]), "=r"((r)[1]) : "r"(addr))
#define MMA16816(d, a, b) \
    asm volatile("mma.sync.aligned.m16n8k16.row.col.f32.bf16.bf16.f32 " \
        "{%0,%1,%2,%3}, {%4,%5,%6,%7}, {%8,%9}, {%0,%1,%2,%3};" \
        : "+f"((d)[0]), "+f"((d)[1]), "+f"((d)[2]), "+f"((d)[3]) \
        : "r"((a)[0]), "r"((a)[1]), "r"((a)[2]), "r"((a)[3]), \
          "r"((b)[0]), "r"((b)[1]))

#define CP16(dst, src) \
    asm volatile("cp.async.cg.shared.global [%0], [%1], 16;" :: "r"(dst), "l"(src) : "memory")
#define CPCOMMIT() asm volatile("cp.async.commit_group;" ::: "memory")
#define CPWAIT0()  asm volatile("cp.async.wait_group 0;" ::: "memory")

__device__ __forceinline__ uint32_t bf2u(__nv_bfloat16 lo, __nv_bfloat16 hi) {
    union { __nv_bfloat162 b; uint32_t u; } c;
    c.b = __halves2bfloat162(lo, hi);
    return c.u;
}

// ---------------------------------------------------------------------------
// Prep kernels: fp32 -> bf16 hi/lo split (and weight transpose)
// ---------------------------------------------------------------------------
__global__ __launch_bounds__(256) void split_f32(
    const float* __restrict__ s, __nv_bfloat16* __restrict__ hi,
    __nv_bfloat16* __restrict__ lo, int n4)
{
    int i = blockIdx.x * 256 + threadIdx.x;
    if (i >= n4) return;
    float4 v = ((const float4*)s)[i];
    union { __nv_bfloat16 b[4]; uint2 u; } ph, pl;
    float f[4] = {v.x, v.y, v.z, v.w};
#pragma unroll
    for (int j = 0; j < 4; j++) {
        __nv_bfloat16 h = __float2bfloat16(f[j]);
        ph.b[j] = h;
        pl.b[j] = __float2bfloat16(f[j] - __bfloat162float(h));
    }
    ((uint2*)hi)[i] = ph.u;
    ((uint2*)lo)[i] = pl.u;
}

// W[K][N] -> Th/Tl[N][K]  (transpose + split)
__global__ void transpose_split(const float* __restrict__ W,
                                __nv_bfloat16* __restrict__ Th,
                                __nv_bfloat16* __restrict__ Tl, int K, int N)
{
    __shared__ float t[32][33];
    const int k0 = blockIdx.y * 32, n0 = blockIdx.x * 32;
    const int tx = threadIdx.x, ty = threadIdx.y;
    for (int j = ty; j < 32; j += 8)
        t[j][tx] = W[(size_t)(k0 + j) * N + n0 + tx];
    __syncthreads();
    for (int j = ty; j < 32; j += 8) {
        float v = t[tx][j];
        __nv_bfloat16 h = __float2bfloat16(v);
        Th[(size_t)(n0 + j) * K + k0 + tx] = h;
        Tl[(size_t)(n0 + j) * K + k0 + tx] = __float2bfloat16(v - __bfloat162float(h));
    }
}

// ---------------------------------------------------------------------------
// mma.sync GEMM with bf16 hi/lo split (3 passes), fp32 accumulate.
// C[M,N] = A[M,K] @ B[N,K]^T + bias[N]
// mode 0: plain write to C.  mode 1: write Q/K/V bf16 hi/lo (Q pre-scaled).
// ---------------------------------------------------------------------------
#define GT_SMEM (4 * 16384 + 1024)

__global__ __launch_bounds__(256, 2) void gemm_tc(
    const __nv_bfloat16* __restrict__ Ah, const __nv_bfloat16* __restrict__ Al,
    const __nv_bfloat16* __restrict__ Bh, const __nv_bfloat16* __restrict__ Bl,
    const float* __restrict__ bias, float* __restrict__ C,
    int M, int N, int K, int mode)
{
    extern __shared__ char smraw[];
    const uint32_t smem0 = smem_u32(smraw);
    const uint32_t tile  = (smem0 + 1023u) & ~1023u;
    const uint32_t sA_h = tile, sA_l = tile + 16384;
    const uint32_t sB_h = tile + 32768, sB_l = tile + 49152;

    const int tid  = threadIdx.x;
    const int wid  = tid >> 5, lane = tid & 31;
    const int wm   = wid & 1, wn = wid >> 1;        // 2 x 4 warp grid
    const int bm   = blockIdx.y << 7, bn = blockIdx.x << 7;

    uint32_t a_base[4], b_base[4];
#pragma unroll
    for (int mi = 0; mi < 4; mi++) {
        const int rowA = wm * 64 + mi * 16 + (lane & 15);
        a_base[mi] = (uint32_t)rowA * 128 + (((uint32_t)lane >> 4) << 4);
    }
    const int l15 = lane & 15;
#pragma unroll
    for (int ni = 0; ni < 4; ni++) {
        const int rowB = wn * 32 + ni * 8 + (l15 & 7);
        b_base[ni] = (uint32_t)rowB * 128 + (((uint32_t)l15 >> 3) << 4);
    }

    float d[4][4][4];
#pragma unroll
    for (int mi = 0; mi < 4; mi++)
#pragma unroll
        for (int ni = 0; ni < 4; ni++)
#pragma unroll
            for (int k = 0; k < 4; k++) d[mi][ni][k] = 0.f;

    for (int kc = 0; kc < K; kc += 64) {
        __syncthreads();
#pragma unroll
        for (int i = 0; i < 4; i++) {
            const int idx = tid + (i << 8);
            const int r = idx >> 3, c = idx & 7;
            const uint32_t so = SWZ((uint32_t)r * 128 + (uint32_t)c * 16);
            const size_t gA = (size_t)(bm + r) * K + kc + c * 8;
            const size_t gB = (size_t)(bn + r) * K + kc + c * 8;
            uint4 v;
            v = *(const uint4*)(Ah + gA); STS128(sA_h + so, v);
            v = *(const uint4*)(Al + gA); STS128(sA_l + so, v);
            v = *(const uint4*)(Bh + gB); STS128(sB_h + so, v);
            v = *(const uint4*)(Bl + gB); STS128(sB_l + so, v);
        }
        __syncthreads();

#pragma unroll
        for (int ks = 0; ks < 4; ks++) {
            const uint32_t kb = (uint32_t)ks << 5;
            uint32_t fAh[4][4], fAl[4][4], fBh[4][2], fBl[4][2];
#pragma unroll
            for (int mi = 0; mi < 4; mi++) {
                LDSM_X4(fAh[mi], sA_h + SWZ(a_base[mi] + kb));
                LDSM_X4(fAl[mi], sA_l + SWZ(a_base[mi] + kb));
            }
#pragma unroll
            for (int ni = 0; ni < 4; ni++) {
                LDSM_X2(fBh[ni], sB_h + SWZ(b_base[ni] + kb));
                LDSM_X2(fBl[ni], sB_l + SWZ(b_base[ni] + kb));
            }
#pragma unroll
            for (int mi = 0; mi < 4; mi++)
#pragma unroll
                for (int ni = 0; ni < 4; ni++) {
                    MMA16816(d[mi][ni], fAh[mi], fBh[ni]);
                    MMA16816(d[mi][ni], fAh[mi], fBl[ni]);
                    MMA16816(d[mi][ni], fAl[mi], fBh[ni]);
                }
        }
    }

    // ---- epilogue ----
    const int q = lane >> 2;
    const int cpair = (lane & 3) << 1;
#pragma unroll
    for (int ni = 0; ni < 4; ni++) {
        const int n = bn + wn * 32 + ni * 8 + cpair;
        const float2 bs = *(const float2*)(bias + n);
#pragma unroll
        for (int mi = 0; mi < 4; mi++) {
#pragma unroll
            for (int hh = 0; hh < 2; hh++) {
                const int m = bm + wm * 64 + mi * 16 + q + hh * 8;
                float2 v;
                v.x = d[mi][ni][hh * 2 + 0] + bs.x;
                v.y = d[mi][ni][hh * 2 + 1] + bs.y;
                if (mode == 1) {
                    const int cc = n >> 10, hd = (n >> 6) & 15, dd = n & 63;
                    const int bb = m >> 11, ss = m & 2047;
                    const float sc = (cc == 0) ? 0.125f : 1.0f;
                    const float vx = v.x * sc, vy = v.y * sc;
                    const __nv_bfloat16 hx = __float2bfloat16(vx);
                    const __nv_bfloat16 hy = __float2bfloat16(vy);
                    const __nv_bfloat16 lx = __float2bfloat16(vx - __bfloat162float(hx));
                    const __nv_bfloat16 ly = __float2bfloat16(vy - __bfloat162float(hy));
                    const size_t off = ((size_t)(bb * HEADS + hd) * SEQ + ss) * DH + dd;
                    __nv_bfloat16* dh = (cc == 0) ? g_q_h : (cc == 1) ? g_k_h : g_v_h;
                    __nv_bfloat16* dl = (cc == 0) ? g_q_l : (cc == 1) ? g_k_l : g_v_l;
                    *(uint32_t*)(dh + off) = bf2u(hx, hy);
                    *(uint32_t*)(dl + off) = bf2u(lx, ly);
                } else {
                    *(float2*)(C + (size_t)m * N + n) = v;
                }
            }
        }
    }
}

// ---------------------------------------------------------------------------
// Tensor-core flash attention.
// CTA: 128 q-rows x one (b,h).  8 warps x 16 rows.  Key tiles of 64,
// cp.async double-buffered.  QK^T and PV both 3-pass bf16 hi/lo split.
// ---------------------------------------------------------------------------
// smem: Qh 16K | Ql 16K | stage0 {Kh,Kl,Vh,Vl} 32K | stage1 32K  = 96K
#define AT_SMEM (96 * 1024 + 1024)

__global__ __launch_bounds__(256, 1) void attn_mma()
{
    extern __shared__ char smraw[];
    const uint32_t base = (smem_u32(smraw) + 1023u) & ~1023u;
    const uint32_t sQh = base, sQl = base + 16384;
    const uint32_t sStage = base + 32768;       // + s*32768; K_h 0 | K_l 8K | V_h 16K | V_l 24K

    const int tid = threadIdx.x, lane = tid & 31, wid = tid >> 5;
    const int bh = blockIdx.y;                  // b*16 + h
    const int q0 = blockIdx.x << 7;
    const size_t hbase = (size_t)bh * (SEQ * DH);

    // ---- prologue: start loading key-tile 0, stage Q ----
    {
        const size_t rb = hbase;                // kt = 0
        const uint32_t st = sStage;
#pragma unroll
        for (int j = 0; j < 2; j++) {
            const int idx = tid + (j << 8);
            const int r = idx >> 3, c = idx & 7;
            const uint32_t so = SWZ((uint32_t)r * 128 + (uint32_t)c * 16);
            const size_t g = rb + (size_t)r * DH + c * 8;
            CP16(st + so,         g_k_h + g);
            CP16(st + 8192 + so,  g_k_l + g);
            CP16(st + 16384 + so, g_v_h + g);
            CP16(st + 24576 + so, g_v_l + g);
        }
        CPCOMMIT();
    }
    for (int i = tid; i < 1024; i += 256) {
        const int r = i >> 3, c = i & 7;
        const uint32_t so = SWZ((uint32_t)r * 128 + (uint32_t)c * 16);
        const size_t g = hbase + (size_t)(q0 + r) * DH + c * 8;
        uint4 v;
        v = *(const uint4*)(g_q_h + g); STS128(sQh + so, v);
        v = *(const uint4*)(g_q_l + g); STS128(sQl + so, v);
    }
    __syncthreads();

    // Q fragments (persistent): 4 k-steps x 4 regs, hi & lo
    uint32_t qh[4][4], ql[4][4];
    {
        const uint32_t qoff = (uint32_t)(wid * 16 + (lane & 15)) * 128 + ((lane >> 4) << 4);
#pragma unroll
        for (int ks = 0; ks < 4; ks++) {
            LDSM_X4(qh[ks], sQh + SWZ(qoff + ks * 32));
            LDSM_X4(ql[ks], sQl + SWZ(qoff + ks * 32));
        }
    }

    float O[8][4];
#pragma unroll
    for (int nt = 0; nt < 8; nt++)
#pragma unroll
        for (int e = 0; e < 4; e++) O[nt][e] = 0.f;
    float m0 = -3.0e38f, m1 = -3.0e38f, l0 = 0.f, l1 = 0.f;

    // K b-frag addressing (non-trans x4: n16 x k16 per load)
    const int krow = (lane & 7) + ((lane >> 4) << 3);
    const uint32_t kchunk = ((uint32_t)(lane >> 3) & 1) << 4;
    // V b-frag addressing (trans x4: two d-tiles x k16 per load)
    const int vrow_l = lane & 15;
    const uint32_t vchunk = ((uint32_t)lane >> 4) << 4;

    for (int kt = 0; kt < SEQ / 64; kt++) {
        CPWAIT0();
        __syncthreads();

        // issue loads for next tile into other stage (overlaps compute below)
        if (kt + 1 < SEQ / 64) {
            const size_t rb = hbase + (size_t)((kt + 1) << 6) * DH;
            const uint32_t st = sStage + ((kt + 1) & 1) * 32768;
#pragma unroll
            for (int j = 0; j < 2; j++) {
                const int idx = tid + (j << 8);
                const int r = idx >> 3, c = idx & 7;
                const uint32_t so = SWZ((uint32_t)r * 128 + (uint32_t)c * 16);
                const size_t g = rb + (size_t)r * DH + c * 8;
                CP16(st + so,         g_k_h + g);
                CP16(st + 8192 + so,  g_k_l + g);
                CP16(st + 16384 + so, g_v_h + g);
                CP16(st + 24576 + so, g_v_l + g);
            }
            CPCOMMIT();
        }

        const uint32_t stK_h = sStage + (kt & 1) * 32768;
        const uint32_t stK_l = stK_h + 8192;
        const uint32_t stV_h = stK_h + 16384;
        const uint32_t stV_l = stK_h + 24576;

        // ---- S = Qhi*Khi + Qhi*Klo + Qlo*Khi ----
        float S[8][4];
#pragma unroll
        for (int nt = 0; nt < 8; nt++)
#pragma unroll
            for (int e = 0; e < 4; e++) S[nt][e] = 0.f;

#pragma unroll
        for (int ks = 0; ks < 4; ks++) {
            uint32_t kbh[4][4], kbl[4][4];
#pragma unroll
            for (int g = 0; g < 4; g++) {
                const uint32_t off = SWZ((uint32_t)(g * 16 + krow) * 128 + (ks << 5) + kchunk);
                LDSM_X4(kbh[g], stK_h + off);
                LDSM_X4(kbl[g], stK_l + off);
            }
#pragma unroll
            for (int g = 0; g < 4; g++) {
                MMA16816(S[2 * g],     qh[ks], &kbh[g][0]);
                MMA16816(S[2 * g + 1], qh[ks], &kbh[g][2]);
                MMA16816(S[2 * g],     qh[ks], &kbl[g][0]);
                MMA16816(S[2 * g + 1], qh[ks], &kbl[g][2]);
                MMA16816(S[2 * g],     ql[ks], &kbh[g][0]);
                MMA16816(S[2 * g + 1], ql[ks], &kbh[g][2]);
            }
        }

        // ---- online softmax (rows: lane>>2 and +8; quad = lanes xor 1,2) ----
        float rx0 = -3.0e38f, rx1 = -3.0e38f;
#pragma unroll
        for (int nt = 0; nt < 8; nt++) {
            rx0 = fmaxf(rx0, fmaxf(S[nt][0], S[nt][1]));
            rx1 = fmaxf(rx1, fmaxf(S[nt][2], S[nt][3]));
        }
        rx0 = fmaxf(rx0, __shfl_xor_sync(0xffffffffu, rx0, 1));
        rx0 = fmaxf(rx0, __shfl_xor_sync(0xffffffffu, rx0, 2));
        rx1 = fmaxf(rx1, __shfl_xor_sync(0xffffffffu, rx1, 1));
        rx1 = fmaxf(rx1, __shfl_xor_sync(0xffffffffu, rx1, 2));
        const float mn0 = fmaxf(m0, rx0), mn1 = fmaxf(m1, rx1);
        const float a0 = __expf(m0 - mn0), a1 = __expf(m1 - mn1);
        float s0 = 0.f, s1 = 0.f;
#pragma unroll
        for (int nt = 0; nt < 8; nt++) {
            S[nt][0] = __expf(S[nt][0] - mn0);
            S[nt][1] = __expf(S[nt][1] - mn0);
            S[nt][2] = __expf(S[nt][2] - mn1);
            S[nt][3] = __expf(S[nt][3] - mn1);
            s0 += S[nt][0] + S[nt][1];
            s1 += S[nt][2] + S[nt][3];
        }
        s0 += __shfl_xor_sync(0xffffffffu, s0, 1);
        s0 += __shfl_xor_sync(0xffffffffu, s0, 2);
        s1 += __shfl_xor_sync(0xffffffffu, s1, 1);
        s1 += __shfl_xor_sync(0xffffffffu, s1, 2);
        l0 = l0 * a0 + s0; l1 = l1 * a1 + s1;
        m0 = mn0; m1 = mn1;
#pragma unroll
        for (int nt = 0; nt < 8; nt++) {
            O[nt][0] *= a0; O[nt][1] *= a0;
            O[nt][2] *= a1; O[nt][3] *= a1;
        }

        // ---- P fragments (hi/lo) directly from S registers ----
        uint32_t ph[4][4], pl[4][4];
#pragma unroll
        for (int c = 0; c < 4; c++) {
#pragma unroll
            for (int j = 0; j < 4; j++) {
                const int nt = 2 * c + (j >> 1);
                const int e0 = (j & 1) * 2;
                const float p0 = S[nt][e0], p1 = S[nt][e0 + 1];
                const __nv_bfloat16 b0 = __float2bfloat16(p0);
                const __nv_bfloat16 b1 = __float2bfloat16(p1);
                ph[c][j] = bf2u(b0, b1);
                pl[c][j] = bf2u(__float2bfloat16(p0 - __bfloat162float(b0)),
                                __float2bfloat16(p1 - __bfloat162float(b1)));
            }
        }

        // ---- O += Ph*Vh + Pl*Vh + Ph*Vl  (V^T via ldmatrix.trans) ----
#pragma unroll
        for (int c = 0; c < 4; c++) {
            uint32_t vbh[4][4], vbl[4][4];
#pragma unroll
            for (int g = 0; g < 4; g++) {
                const uint32_t off =
                    SWZ((uint32_t)(c * 16 + vrow_l) * 128 + ((uint32_t)g << 5) + vchunk);
                LDSM_X4T(vbh[g], stV_h + off);
                LDSM_X4T(vbl[g], stV_l + off);
            }
#pragma unroll
            for (int g = 0; g < 4; g++) {
                MMA16816(O[2 * g],     ph[c], &vbh[g][0]);
                MMA16816(O[2 * g + 1], ph[c], &vbh[g][2]);
                MMA16816(O[2 * g],     pl[c], &vbh[g][0]);
                MMA16816(O[2 * g + 1], pl[c], &vbh[g][2]);
                MMA16816(O[2 * g],     ph[c], &vbl[g][0]);
                MMA16816(O[2 * g + 1], ph[c], &vbl[g][2]);
            }
        }
    }

    // ---- finalize: O/l -> bf16 hi/lo -> g_attn [b][s][h*64+d] ----
    const float inv0 = 1.0f / l0, inv1 = 1.0f / l1;
    const int b_ = bh >> 4, h_ = bh & 15;
    const int row0 = q0 + wid * 16 + (lane >> 2);
#pragma unroll
    for (int nt = 0; nt < 8; nt++) {
        const int dcol = nt * 8 + ((lane & 3) << 1);
#pragma unroll
        for (int hh = 0; hh < 2; hh++) {
            const int row = row0 + hh * 8;
            const float inv = hh ? inv1 : inv0;
            const float v0 = O[nt][hh * 2 + 0] * inv;
            const float v1 = O[nt][hh * 2 + 1] * inv;
            const __nv_bfloat16 h0 = __float2bfloat16(v0);
            const __nv_bfloat16 h1 = __float2bfloat16(v1);
            const size_t off = ((size_t)b_ * SEQ + row) * HID + h_ * DH + dcol;
            *(uint32_t*)(g_attn_h + off) = bf2u(h0, h1);
            *(uint32_t*)(g_attn_l + off) =
                bf2u(__float2bfloat16(v0 - __bfloat162float(h0)),
                     __float2bfloat16(v1 - __bfloat162float(h1)));
        }
    }
}

// ---------------------------------------------------------------------------
extern "C" void kernel_launch(void* const* d_in, const int* in_sizes, int n_in,
                              void* d_out, int out_size)
{
    const float* x    = (const float*)d_in[0];
    const float* Wqkv = (const float*)d_in[1];
    const float* bqkv = (const float*)d_in[2];
    const float* Wout = (const float*)d_in[3];
    const float* bout = (const float*)d_in[4];
    float* out = (float*)d_out;

    cudaFuncSetAttribute(gemm_tc,
                         cudaFuncAttributeMaxDynamicSharedMemorySize, GT_SMEM);
    cudaFuncSetAttribute(attn_mma,
                         cudaFuncAttributeMaxDynamicSharedMemorySize, AT_SMEM);

    __nv_bfloat16 *xh, *xl, *wqh, *wql, *woh, *wol, *ath, *atl;
    cudaGetSymbolAddress((void**)&xh,  g_x_h);
    cudaGetSymbolAddress((void**)&xl,  g_x_l);
    cudaGetSymbolAddress((void**)&wqh, g_wq_h);
    cudaGetSymbolAddress((void**)&wql, g_wq_l);
    cudaGetSymbolAddress((void**)&woh, g_wo_h);
    cudaGetSymbolAddress((void**)&wol, g_wo_l);
    cudaGetSymbolAddress((void**)&ath, g_attn_h);
    cudaGetSymbolAddress((void**)&atl, g_attn_l);

    // 0) prep: split x; transpose+split weights
    split_f32<<<(MTOT * HID / 4 + 255) / 256, 256>>>(x, xh, xl, MTOT * HID / 4);
    transpose_split<<<dim3(3 * HID / 32, HID / 32), dim3(32, 8)>>>(Wqkv, wqh, wql, HID, 3 * HID);
    transpose_split<<<dim3(HID / 32, HID / 32), dim3(32, 8)>>>(Wout, woh, wol, HID, HID);

    // 1) QKV projection -> Q/K/V bf16 hi/lo (Q pre-scaled by 1/8)
    gemm_tc<<<dim3(3 * HID / 128, MTOT / 128), 256, GT_SMEM>>>(
        xh, xl, wqh, wql, bqkv, nullptr, MTOT, 3 * HID, HID, 1);

    // 2) Tensor-core flash attention -> g_attn_h/l
    attn_mma<<<dim3(SEQ / 128, NBH), 256, AT_SMEM>>>();

    // 3) Output projection + bias -> out
    gemm_tc<<<dim3(HID / 128, MTOT / 128), 256, GT_SMEM>>>(
        ath, atl, woh, wol, bout, out, MTOT, HID, HID, 0);
}

// round 12
// speedup vs baseline: 2.0818x; 1.0279x over previous
#include <cuda_runtime.h>
#include <cuda_bf16.h>
#include <cstdint>
#include <math.h>

// Problem constants
#define BATCH   2
#define SEQ     2048
#define HID     1024
#define HEADS   16
#define DH      64
#define MTOT    (BATCH * SEQ)          // 4096
#define NBH     (BATCH * HEADS)        // 32

// ---------------------------------------------------------------------------
// Scratch (device globals — no allocation allowed)
// ---------------------------------------------------------------------------
#define QKV_ELEMS ((size_t)NBH * SEQ * DH)
__device__ __nv_bfloat16 g_q_h[QKV_ELEMS], g_q_l[QKV_ELEMS];
__device__ __nv_bfloat16 g_k_h[QKV_ELEMS], g_k_l[QKV_ELEMS];
__device__ __nv_bfloat16 g_v_h[QKV_ELEMS], g_v_l[QKV_ELEMS];
__device__ __nv_bfloat16 g_attn_h[(size_t)MTOT * HID];
__device__ __nv_bfloat16 g_attn_l[(size_t)MTOT * HID];
__device__ __nv_bfloat16 g_x_h[(size_t)MTOT * HID];
__device__ __nv_bfloat16 g_x_l[(size_t)MTOT * HID];
__device__ __nv_bfloat16 g_wq_h[(size_t)3 * HID * HID];   // [3072][1024] = W_qkv^T
__device__ __nv_bfloat16 g_wq_l[(size_t)3 * HID * HID];
__device__ __nv_bfloat16 g_wo_h[(size_t)HID * HID];       // [1024][1024] = W_out^T
__device__ __nv_bfloat16 g_wo_l[(size_t)HID * HID];

// ---------------------------------------------------------------------------
// PTX helpers (baseline sm_103 ISA: ldmatrix + mma.sync + cp.async)
// ---------------------------------------------------------------------------
__device__ __forceinline__ uint32_t smem_u32(const void* p) {
    uint32_t a;
    asm("{ .reg .u64 t; cvta.to.shared.u64 t, %1; cvt.u32.u64 %0, t; }" : "=r"(a) : "l"(p));
    return a;
}
#define SWZ(o) ((o) ^ (((o) >> 3) & 0x70))
#define STS128(addr, v) \
    asm volatile("st.shared.v4.b32 [%0], {%1,%2,%3,%4};" \
                 :: "r"(addr), "r"(v.x), "r"(v.y), "r"(v.z), "r"(v.w) : "memory")

#define LDSM_X4(r, addr) \
    asm volatile("ldmatrix.sync.aligned.m8n8.x4.shared.b16 {%0,%1,%2,%3}, [%4];" \
        : "=r"((r)[0]), "=r"((r)[1]), "=r"((r)[2]), "=r"((r)[3]) : "r"(addr))
#define LDSM_X4T(r, addr) \
    asm volatile("ldmatrix.sync.aligned.m8n8.x4.trans.shared.b16 {%0,%1,%2,%3}, [%4];" \
        : "=r"((r)[0]), "=r"((r)[1]), "=r"((r)[2]), "=r"((r)[3]) : "r"(addr))
#define LDSM_X2(r, addr) \
    asm volatile("ldmatrix.sync.aligned.m8n8.x2.shared.b16 {%0,%1}, [%2];" \
        : "=r"((r)[0]), "=r"((r)[1]) : "r"(addr))
#define MMA16816(d, a, b) \
    asm volatile("mma.sync.aligned.m16n8k16.row.col.f32.bf16.bf16.f32 " \
        "{%0,%1,%2,%3}, {%4,%5,%6,%7}, {%8,%9}, {%0,%1,%2,%3};" \
        : "+f"((d)[0]), "+f"((d)[1]), "+f"((d)[2]), "+f"((d)[3]) \
        : "r"((a)[0]), "r"((a)[1]), "r"((a)[2]), "r"((a)[3]), \
          "r"((b)[0]), "r"((b)[1]))

#define CP16(dst, src) \
    asm volatile("cp.async.cg.shared.global [%0], [%1], 16;" :: "r"(dst), "l"(src) : "memory")
#define CPCOMMIT() asm volatile("cp.async.commit_group;" ::: "memory")
#define CPWAIT0()  asm volatile("cp.async.wait_group 0;" ::: "memory")

__device__ __forceinline__ uint32_t bf2u(__nv_bfloat16 lo, __nv_bfloat16 hi) {
    union { __nv_bfloat162 b; uint32_t u; } c;
    c.b = __halves2bfloat162(lo, hi);
    return c.u;
}

// ---------------------------------------------------------------------------
// Prep kernels: fp32 -> bf16 hi/lo split (and weight transpose)
// ---------------------------------------------------------------------------
__global__ __launch_bounds__(256) void split_f32(
    const float* __restrict__ s, __nv_bfloat16* __restrict__ hi,
    __nv_bfloat16* __restrict__ lo, int n4)
{
    int i = blockIdx.x * 256 + threadIdx.x;
    if (i >= n4) return;
    float4 v = ((const float4*)s)[i];
    union { __nv_bfloat16 b[4]; uint2 u; } ph, pl;
    float f[4] = {v.x, v.y, v.z, v.w};
#pragma unroll
    for (int j = 0; j < 4; j++) {
        __nv_bfloat16 h = __float2bfloat16(f[j]);
        ph.b[j] = h;
        pl.b[j] = __float2bfloat16(f[j] - __bfloat162float(h));
    }
    ((uint2*)hi)[i] = ph.u;
    ((uint2*)lo)[i] = pl.u;
}

// W[K][N] -> Th/Tl[N][K]  (transpose + split)
__global__ void transpose_split(const float* __restrict__ W,
                                __nv_bfloat16* __restrict__ Th,
                                __nv_bfloat16* __restrict__ Tl, int K, int N)
{
    __shared__ float t[32][33];
    const int k0 = blockIdx.y * 32, n0 = blockIdx.x * 32;
    const int tx = threadIdx.x, ty = threadIdx.y;
    for (int j = ty; j < 32; j += 8)
        t[j][tx] = W[(size_t)(k0 + j) * N + n0 + tx];
    __syncthreads();
    for (int j = ty; j < 32; j += 8) {
        float v = t[tx][j];
        __nv_bfloat16 h = __float2bfloat16(v);
        Th[(size_t)(n0 + j) * K + k0 + tx] = h;
        Tl[(size_t)(n0 + j) * K + k0 + tx] = __float2bfloat16(v - __bfloat162float(h));
    }
}

// ---------------------------------------------------------------------------
// mma.sync GEMM, bf16 hi/lo split (3 passes), fp32 accumulate.
// cp.async 2-stage pipelined mainloop (K-chunk 64, 64KB/stage, 1 CTA/SM).
// C[M,N] = A[M,K] @ B[N,K]^T + bias[N]
// mode 0: plain write to C.  mode 1: write Q/K/V bf16 hi/lo (Q pre-scaled).
// ---------------------------------------------------------------------------
#define GT_SMEM (128 * 1024 + 1024)

__global__ __launch_bounds__(256, 1) void gemm_tc(
    const __nv_bfloat16* __restrict__ Ah, const __nv_bfloat16* __restrict__ Al,
    const __nv_bfloat16* __restrict__ Bh, const __nv_bfloat16* __restrict__ Bl,
    const float* __restrict__ bias, float* __restrict__ C,
    int M, int N, int K, int mode)
{
    extern __shared__ char smraw[];
    const uint32_t tile = (smem_u32(smraw) + 1023u) & ~1023u;
    // stage s at tile + s*65536: A_h 0 | A_l 16K | B_h 32K | B_l 48K

    const int tid  = threadIdx.x;
    const int wid  = tid >> 5, lane = tid & 31;
    const int wm   = wid & 1, wn = wid >> 1;        // 2 x 4 warp grid
    const int bm   = blockIdx.y << 7, bn = blockIdx.x << 7;

    uint32_t a_base[4], b_base[4];
#pragma unroll
    for (int mi = 0; mi < 4; mi++) {
        const int rowA = wm * 64 + mi * 16 + (lane & 15);
        a_base[mi] = (uint32_t)rowA * 128 + (((uint32_t)lane >> 4) << 4);
    }
    const int l15 = lane & 15;
#pragma unroll
    for (int ni = 0; ni < 4; ni++) {
        const int rowB = wn * 32 + ni * 8 + (l15 & 7);
        b_base[ni] = (uint32_t)rowB * 128 + (((uint32_t)l15 >> 3) << 4);
    }

    // loader chunk addressing (shared by prologue and steady state)
    const int lr = tid >> 1;                 // unused placeholder removal
    (void)lr;

    float d[4][4][4];
#pragma unroll
    for (int mi = 0; mi < 4; mi++)
#pragma unroll
        for (int ni = 0; ni < 4; ni++)
#pragma unroll
            for (int k = 0; k < 4; k++) d[mi][ni][k] = 0.f;

    // ---- prologue: issue chunk 0 into stage 0 ----
    {
        const uint32_t st = tile;
#pragma unroll
        for (int i = 0; i < 4; i++) {
            const int idx = tid + (i << 8);
            const int r = idx >> 3, c = idx & 7;
            const uint32_t so = SWZ((uint32_t)r * 128 + (uint32_t)c * 16);
            const size_t gA = (size_t)(bm + r) * K + c * 8;
            const size_t gB = (size_t)(bn + r) * K + c * 8;
            CP16(st + so,         Ah + gA);
            CP16(st + 16384 + so, Al + gA);
            CP16(st + 32768 + so, Bh + gB);
            CP16(st + 49152 + so, Bl + gB);
        }
        CPCOMMIT();
    }

    int stg = 0;
    for (int kc = 0; kc < K; kc += 64, stg ^= 1) {
        CPWAIT0();
        __syncthreads();

        if (kc + 64 < K) {
            const uint32_t st = tile + (uint32_t)(stg ^ 1) * 65536u;
#pragma unroll
            for (int i = 0; i < 4; i++) {
                const int idx = tid + (i << 8);
                const int r = idx >> 3, c = idx & 7;
                const uint32_t so = SWZ((uint32_t)r * 128 + (uint32_t)c * 16);
                const size_t gA = (size_t)(bm + r) * K + kc + 64 + c * 8;
                const size_t gB = (size_t)(bn + r) * K + kc + 64 + c * 8;
                CP16(st + so,         Ah + gA);
                CP16(st + 16384 + so, Al + gA);
                CP16(st + 32768 + so, Bh + gB);
                CP16(st + 49152 + so, Bl + gB);
            }
            CPCOMMIT();
        }

        const uint32_t sA_h = tile + (uint32_t)stg * 65536u;
        const uint32_t sA_l = sA_h + 16384, sB_h = sA_h + 32768, sB_l = sA_h + 49152;

#pragma unroll
        for (int ks = 0; ks < 4; ks++) {
            const uint32_t kb = (uint32_t)ks << 5;
            uint32_t fAh[4][4], fAl[4][4], fBh[4][2], fBl[4][2];
#pragma unroll
            for (int mi = 0; mi < 4; mi++) {
                LDSM_X4(fAh[mi], sA_h + SWZ(a_base[mi] + kb));
                LDSM_X4(fAl[mi], sA_l + SWZ(a_base[mi] + kb));
            }
#pragma unroll
            for (int ni = 0; ni < 4; ni++) {
                LDSM_X2(fBh[ni], sB_h + SWZ(b_base[ni] + kb));
                LDSM_X2(fBl[ni], sB_l + SWZ(b_base[ni] + kb));
            }
#pragma unroll
            for (int mi = 0; mi < 4; mi++)
#pragma unroll
                for (int ni = 0; ni < 4; ni++) {
                    MMA16816(d[mi][ni], fAh[mi], fBh[ni]);
                    MMA16816(d[mi][ni], fAh[mi], fBl[ni]);
                    MMA16816(d[mi][ni], fAl[mi], fBh[ni]);
                }
        }
    }

    // ---- epilogue ----
    const int q = lane >> 2;
    const int cpair = (lane & 3) << 1;
#pragma unroll
    for (int ni = 0; ni < 4; ni++) {
        const int n = bn + wn * 32 + ni * 8 + cpair;
        const float2 bs = *(const float2*)(bias + n);
#pragma unroll
        for (int mi = 0; mi < 4; mi++) {
#pragma unroll
            for (int hh = 0; hh < 2; hh++) {
                const int m = bm + wm * 64 + mi * 16 + q + hh * 8;
                float2 v;
                v.x = d[mi][ni][hh * 2 + 0] + bs.x;
                v.y = d[mi][ni][hh * 2 + 1] + bs.y;
                if (mode == 1) {
                    const int cc = n >> 10, hd = (n >> 6) & 15, dd = n & 63;
                    const int bb = m >> 11, ss = m & 2047;
                    const float sc = (cc == 0) ? 0.125f : 1.0f;
                    const float vx = v.x * sc, vy = v.y * sc;
                    const __nv_bfloat16 hx = __float2bfloat16(vx);
                    const __nv_bfloat16 hy = __float2bfloat16(vy);
                    const __nv_bfloat16 lx = __float2bfloat16(vx - __bfloat162float(hx));
                    const __nv_bfloat16 ly = __float2bfloat16(vy - __bfloat162float(hy));
                    const size_t off = ((size_t)(bb * HEADS + hd) * SEQ + ss) * DH + dd;
                    __nv_bfloat16* dh = (cc == 0) ? g_q_h : (cc == 1) ? g_k_h : g_v_h;
                    __nv_bfloat16* dl = (cc == 0) ? g_q_l : (cc == 1) ? g_k_l : g_v_l;
                    *(uint32_t*)(dh + off) = bf2u(hx, hy);
                    *(uint32_t*)(dl + off) = bf2u(lx, ly);
                } else {
                    *(float2*)(C + (size_t)m * N + n) = v;
                }
            }
        }
    }
}

// ---------------------------------------------------------------------------
// Tensor-core flash attention, v2: 128 threads / 4 warps per CTA,
// 128 q-rows per CTA => each warp owns 32 rows (2 m-frags). This halves
// K/V fragment LDS traffic per q-row (the R11 bottleneck). 64-key tiles,
// cp.async double-buffered. QK^T and PV 3-pass bf16 hi/lo split.
// smem: Qh 16K | Ql 16K | stage0 32K | stage1 32K = 96K -> 2 CTAs/SM.
// ---------------------------------------------------------------------------
#define AT_SMEM (96 * 1024 + 1024)

__global__ __launch_bounds__(128, 2) void attn_mma()
{
    extern __shared__ char smraw[];
    const uint32_t base = (smem_u32(smraw) + 1023u) & ~1023u;
    const uint32_t sQh = base, sQl = base + 16384;
    const uint32_t sStage = base + 32768;  // + s*32768: Kh 0 | Kl 8K | Vh 16K | Vl 24K

    const int tid = threadIdx.x, lane = tid & 31, wid = tid >> 5;
    const int bh = blockIdx.y;
    const int q0 = blockIdx.x << 7;
    const size_t hbase = (size_t)bh * (SEQ * DH);

    // ---- prologue: cp.async key-tile 0 ----
    {
        const uint32_t st = sStage;
#pragma unroll
        for (int j = 0; j < 4; j++) {
            const int idx = tid + (j << 7);        // 0..511
            const int r = idx >> 3, c = idx & 7;
            const uint32_t so = SWZ((uint32_t)r * 128 + (uint32_t)c * 16);
            const size_t g = hbase + (size_t)r * DH + c * 8;
            CP16(st + so,         g_k_h + g);
            CP16(st + 8192 + so,  g_k_l + g);
            CP16(st + 16384 + so, g_v_h + g);
            CP16(st + 24576 + so, g_v_l + g);
        }
        CPCOMMIT();
    }
    // stage Q (one-time)
    for (int i = tid; i < 1024; i += 128) {
        const int r = i >> 3, c = i & 7;
        const uint32_t so = SWZ((uint32_t)r * 128 + (uint32_t)c * 16);
        const size_t g = hbase + (size_t)(q0 + r) * DH + c * 8;
        uint4 v;
        v = *(const uint4*)(g_q_h + g); STS128(sQh + so, v);
        v = *(const uint4*)(g_q_l + g); STS128(sQl + so, v);
    }
    __syncthreads();

    // Q fragments (persistent): 2 m-frags x 4 k-steps, hi & lo
    uint32_t qh[2][4][4], ql[2][4][4];
#pragma unroll
    for (int mi = 0; mi < 2; mi++) {
        const uint32_t qoff =
            (uint32_t)(wid * 32 + mi * 16 + (lane & 15)) * 128 + ((lane >> 4) << 4);
#pragma unroll
        for (int ks = 0; ks < 4; ks++) {
            LDSM_X4(qh[mi][ks], sQh + SWZ(qoff + ks * 32));
            LDSM_X4(ql[mi][ks], sQl + SWZ(qoff + ks * 32));
        }
    }

    float O[2][8][4];
#pragma unroll
    for (int mi = 0; mi < 2; mi++)
#pragma unroll
        for (int nt = 0; nt < 8; nt++)
#pragma unroll
            for (int e = 0; e < 4; e++) O[mi][nt][e] = 0.f;
    float m_i[2][2], l_i[2][2];
#pragma unroll
    for (int mi = 0; mi < 2; mi++) {
        m_i[mi][0] = m_i[mi][1] = -3.0e38f;
        l_i[mi][0] = l_i[mi][1] = 0.f;
    }

    const int krow = (lane & 7) + ((lane >> 4) << 3);
    const uint32_t kchunk = ((uint32_t)(lane >> 3) & 1) << 4;
    const int vrow_l = lane & 15;
    const uint32_t vchunk = ((uint32_t)lane >> 4) << 4;

    for (int kt = 0; kt < SEQ / 64; kt++) {
        CPWAIT0();
        __syncthreads();

        if (kt + 1 < SEQ / 64) {
            const size_t rb = hbase + (size_t)((kt + 1) << 6) * DH;
            const uint32_t st = sStage + ((kt + 1) & 1) * 32768;
#pragma unroll
            for (int j = 0; j < 4; j++) {
                const int idx = tid + (j << 7);
                const int r = idx >> 3, c = idx & 7;
                const uint32_t so = SWZ((uint32_t)r * 128 + (uint32_t)c * 16);
                const size_t g = rb + (size_t)r * DH + c * 8;
                CP16(st + so,         g_k_h + g);
                CP16(st + 8192 + so,  g_k_l + g);
                CP16(st + 16384 + so, g_v_h + g);
                CP16(st + 24576 + so, g_v_l + g);
            }
            CPCOMMIT();
        }

        const uint32_t stK_h = sStage + (kt & 1) * 32768;
        const uint32_t stK_l = stK_h + 8192;
        const uint32_t stV_h = stK_h + 16384;
        const uint32_t stV_l = stK_h + 24576;

        // ---- S = Qhi*Khi + Qhi*Klo + Qlo*Khi ----
        float S[2][8][4];
#pragma unroll
        for (int mi = 0; mi < 2; mi++)
#pragma unroll
            for (int nt = 0; nt < 8; nt++)
#pragma unroll
                for (int e = 0; e < 4; e++) S[mi][nt][e] = 0.f;

#pragma unroll
        for (int ks = 0; ks < 4; ks++) {
#pragma unroll
            for (int g = 0; g < 4; g++) {
                uint32_t kbh[4], kbl[4];
                const uint32_t off = SWZ((uint32_t)(g * 16 + krow) * 128 + (ks << 5) + kchunk);
                LDSM_X4(kbh, stK_h + off);
                LDSM_X4(kbl, stK_l + off);
#pragma unroll
                for (int mi = 0; mi < 2; mi++) {
                    MMA16816(S[mi][2 * g],     qh[mi][ks], &kbh[0]);
                    MMA16816(S[mi][2 * g + 1], qh[mi][ks], &kbh[2]);
                    MMA16816(S[mi][2 * g],     qh[mi][ks], &kbl[0]);
                    MMA16816(S[mi][2 * g + 1], qh[mi][ks], &kbl[2]);
                    MMA16816(S[mi][2 * g],     ql[mi][ks], &kbh[0]);
                    MMA16816(S[mi][2 * g + 1], ql[mi][ks], &kbh[2]);
                }
            }
        }

        // ---- online softmax per m-frag ----
#pragma unroll
        for (int mi = 0; mi < 2; mi++) {
            float rx0 = -3.0e38f, rx1 = -3.0e38f;
#pragma unroll
            for (int nt = 0; nt < 8; nt++) {
                rx0 = fmaxf(rx0, fmaxf(S[mi][nt][0], S[mi][nt][1]));
                rx1 = fmaxf(rx1, fmaxf(S[mi][nt][2], S[mi][nt][3]));
            }
            rx0 = fmaxf(rx0, __shfl_xor_sync(0xffffffffu, rx0, 1));
            rx0 = fmaxf(rx0, __shfl_xor_sync(0xffffffffu, rx0, 2));
            rx1 = fmaxf(rx1, __shfl_xor_sync(0xffffffffu, rx1, 1));
            rx1 = fmaxf(rx1, __shfl_xor_sync(0xffffffffu, rx1, 2));
            const float mn0 = fmaxf(m_i[mi][0], rx0), mn1 = fmaxf(m_i[mi][1], rx1);
            const float a0 = __expf(m_i[mi][0] - mn0), a1 = __expf(m_i[mi][1] - mn1);
            float s0 = 0.f, s1 = 0.f;
#pragma unroll
            for (int nt = 0; nt < 8; nt++) {
                S[mi][nt][0] = __expf(S[mi][nt][0] - mn0);
                S[mi][nt][1] = __expf(S[mi][nt][1] - mn0);
                S[mi][nt][2] = __expf(S[mi][nt][2] - mn1);
                S[mi][nt][3] = __expf(S[mi][nt][3] - mn1);
                s0 += S[mi][nt][0] + S[mi][nt][1];
                s1 += S[mi][nt][2] + S[mi][nt][3];
            }
            s0 += __shfl_xor_sync(0xffffffffu, s0, 1);
            s0 += __shfl_xor_sync(0xffffffffu, s0, 2);
            s1 += __shfl_xor_sync(0xffffffffu, s1, 1);
            s1 += __shfl_xor_sync(0xffffffffu, s1, 2);
            l_i[mi][0] = l_i[mi][0] * a0 + s0;
            l_i[mi][1] = l_i[mi][1] * a1 + s1;
            m_i[mi][0] = mn0; m_i[mi][1] = mn1;
#pragma unroll
            for (int nt = 0; nt < 8; nt++) {
                O[mi][nt][0] *= a0; O[mi][nt][1] *= a0;
                O[mi][nt][2] *= a1; O[mi][nt][3] *= a1;
            }
        }

        // ---- PV: O += Ph*Vh + Pl*Vh + Ph*Vl (V^T via ldmatrix.trans) ----
#pragma unroll
        for (int c = 0; c < 4; c++) {
            uint32_t ph[2][4], pl[2][4];
#pragma unroll
            for (int mi = 0; mi < 2; mi++)
#pragma unroll
                for (int j = 0; j < 4; j++) {
                    const int nt = 2 * c + (j >> 1);
                    const int e0 = (j & 1) * 2;
                    const float p0 = S[mi][nt][e0], p1 = S[mi][nt][e0 + 1];
                    const __nv_bfloat16 b0 = __float2bfloat16(p0);
                    const __nv_bfloat16 b1 = __float2bfloat16(p1);
                    ph[mi][j] = bf2u(b0, b1);
                    pl[mi][j] = bf2u(__float2bfloat16(p0 - __bfloat162float(b0)),
                                     __float2bfloat16(p1 - __bfloat162float(b1)));
                }
#pragma unroll
            for (int g = 0; g < 4; g++) {
                uint32_t vbh[4], vbl[4];
                const uint32_t off =
                    SWZ((uint32_t)(c * 16 + vrow_l) * 128 + ((uint32_t)g << 5) + vchunk);
                LDSM_X4T(vbh, stV_h + off);
                LDSM_X4T(vbl, stV_l + off);
#pragma unroll
                for (int mi = 0; mi < 2; mi++) {
                    MMA16816(O[mi][2 * g],     ph[mi], &vbh[0]);
                    MMA16816(O[mi][2 * g + 1], ph[mi], &vbh[2]);
                    MMA16816(O[mi][2 * g],     pl[mi], &vbh[0]);
                    MMA16816(O[mi][2 * g + 1], pl[mi], &vbh[2]);
                    MMA16816(O[mi][2 * g],     ph[mi], &vbl[0]);
                    MMA16816(O[mi][2 * g + 1], ph[mi], &vbl[2]);
                }
            }
        }
    }

    // ---- finalize: O/l -> bf16 hi/lo -> g_attn [b][s][h*64+d] ----
    const int b_ = bh >> 4, h_ = bh & 15;
#pragma unroll
    for (int mi = 0; mi < 2; mi++) {
        const float inv0 = 1.0f / l_i[mi][0], inv1 = 1.0f / l_i[mi][1];
        const int row0 = q0 + wid * 32 + mi * 16 + (lane >> 2);
#pragma unroll
        for (int nt = 0; nt < 8; nt++) {
            const int dcol = nt * 8 + ((lane & 3) << 1);
#pragma unroll
            for (int hh = 0; hh < 2; hh++) {
                const int row = row0 + hh * 8;
                const float inv = hh ? inv1 : inv0;
                const float v0 = O[mi][nt][hh * 2 + 0] * inv;
                const float v1 = O[mi][nt][hh * 2 + 1] * inv;
                const __nv_bfloat16 h0 = __float2bfloat16(v0);
                const __nv_bfloat16 h1 = __float2bfloat16(v1);
                const size_t off = ((size_t)b_ * SEQ + row) * HID + h_ * DH + dcol;
                *(uint32_t*)(g_attn_h + off) = bf2u(h0, h1);
                *(uint32_t*)(g_attn_l + off) =
                    bf2u(__float2bfloat16(v0 - __bfloat162float(h0)),
                         __float2bfloat16(v1 - __bfloat162float(h1)));
            }
        }
    }
}

// ---------------------------------------------------------------------------
extern "C" void kernel_launch(void* const* d_in, const int* in_sizes, int n_in,
                              void* d_out, int out_size)
{
    const float* x    = (const float*)d_in[0];
    const float* Wqkv = (const float*)d_in[1];
    const float* bqkv = (const float*)d_in[2];
    const float* Wout = (const float*)d_in[3];
    const float* bout = (const float*)d_in[4];
    float* out = (float*)d_out;

    cudaFuncSetAttribute(gemm_tc,
                         cudaFuncAttributeMaxDynamicSharedMemorySize, GT_SMEM);
    cudaFuncSetAttribute(attn_mma,
                         cudaFuncAttributeMaxDynamicSharedMemorySize, AT_SMEM);

    __nv_bfloat16 *xh, *xl, *wqh, *wql, *woh, *wol, *ath, *atl;
    cudaGetSymbolAddress((void**)&xh,  g_x_h);
    cudaGetSymbolAddress((void**)&xl,  g_x_l);
    cudaGetSymbolAddress((void**)&wqh, g_wq_h);
    cudaGetSymbolAddress((void**)&wql, g_wq_l);
    cudaGetSymbolAddress((void**)&woh, g_wo_h);
    cudaGetSymbolAddress((void**)&wol, g_wo_l);
    cudaGetSymbolAddress((void**)&ath, g_attn_h);
    cudaGetSymbolAddress((void**)&atl, g_attn_l);

    // 0) prep: split x; transpose+split weights
    split_f32<<<(MTOT * HID / 4 + 255) / 256, 256>>>(x, xh, xl, MTOT * HID / 4);
    transpose_split<<<dim3(3 * HID / 32, HID / 32), dim3(32, 8)>>>(Wqkv, wqh, wql, HID, 3 * HID);
    transpose_split<<<dim3(HID / 32, HID / 32), dim3(32, 8)>>>(Wout, woh, wol, HID, HID);

    // 1) QKV projection -> Q/K/V bf16 hi/lo (Q pre-scaled by 1/8)
    gemm_tc<<<dim3(3 * HID / 128, MTOT / 128), 256, GT_SMEM>>>(
        xh, xl, wqh, wql, bqkv, nullptr, MTOT, 3 * HID, HID, 1);

    // 2) Tensor-core flash attention -> g_attn_h/l
    attn_mma<<<dim3(SEQ / 128, NBH), 128, AT_SMEM>>>();

    // 3) Output projection + bias -> out
    gemm_tc<<<dim3(HID / 128, MTOT / 128), 256, GT_SMEM>>>(
        ath, atl, woh, wol, bout, out, MTOT, HID, HID, 0);
}

// round 13
// speedup vs baseline: 2.1009x; 1.0092x over previous
#include <cuda_runtime.h>
#include <cuda_bf16.h>
#include <cstdint>
#include <math.h>

// Problem constants
#define BATCH   2
#define SEQ     2048
#define HID     1024
#define HEADS   16
#define DH      64
#define MTOT    (BATCH * SEQ)          // 4096
#define NBH     (BATCH * HEADS)        // 32

// ---------------------------------------------------------------------------
// Scratch (device globals — no allocation allowed)
// ---------------------------------------------------------------------------
#define QKV_ELEMS ((size_t)NBH * SEQ * DH)
__device__ __nv_bfloat16 g_q_h[QKV_ELEMS], g_q_l[QKV_ELEMS];
__device__ __nv_bfloat16 g_k_h[QKV_ELEMS], g_k_l[QKV_ELEMS];
__device__ __nv_bfloat16 g_v_h[QKV_ELEMS], g_v_l[QKV_ELEMS];
__device__ __nv_bfloat16 g_attn_h[(size_t)MTOT * HID];
__device__ __nv_bfloat16 g_attn_l[(size_t)MTOT * HID];
__device__ __nv_bfloat16 g_x_h[(size_t)MTOT * HID];
__device__ __nv_bfloat16 g_x_l[(size_t)MTOT * HID];
__device__ __nv_bfloat16 g_wq_h[(size_t)3 * HID * HID];   // [3072][1024] = W_qkv^T
__device__ __nv_bfloat16 g_wq_l[(size_t)3 * HID * HID];
__device__ __nv_bfloat16 g_wo_h[(size_t)HID * HID];       // [1024][1024] = W_out^T
__device__ __nv_bfloat16 g_wo_l[(size_t)HID * HID];

// ---------------------------------------------------------------------------
// PTX helpers (baseline sm_103 ISA: ldmatrix + mma.sync + cp.async)
// ---------------------------------------------------------------------------
__device__ __forceinline__ uint32_t smem_u32(const void* p) {
    uint32_t a;
    asm("{ .reg .u64 t; cvta.to.shared.u64 t, %1; cvt.u32.u64 %0, t; }" : "=r"(a) : "l"(p));
    return a;
}
#define SWZ(o) ((o) ^ (((o) >> 3) & 0x70))
#define STS128(addr, v) \
    asm volatile("st.shared.v4.b32 [%0], {%1,%2,%3,%4};" \
                 :: "r"(addr), "r"(v.x), "r"(v.y), "r"(v.z), "r"(v.w) : "memory")

#define LDSM_X4(r, addr) \
    asm volatile("ldmatrix.sync.aligned.m8n8.x4.shared.b16 {%0,%1,%2,%3}, [%4];" \
        : "=r"((r)[0]), "=r"((r)[1]), "=r"((r)[2]), "=r"((r)[3]) : "r"(addr))
#define LDSM_X4T(r, addr) \
    asm volatile("ldmatrix.sync.aligned.m8n8.x4.trans.shared.b16 {%0,%1,%2,%3}, [%4];" \
        : "=r"((r)[0]), "=r"((r)[1]), "=r"((r)[2]), "=r"((r)[3]) : "r"(addr))
#define LDSM_X2(r, addr) \
    asm volatile("ldmatrix.sync.aligned.m8n8.x2.shared.b16 {%0,%1}, [%2];" \
        : "=r"((r)[0]), "=r"((r)[1]) : "r"(addr))
#define MMA16816(d, a, b) \
    asm volatile("mma.sync.aligned.m16n8k16.row.col.f32.bf16.bf16.f32 " \
        "{%0,%1,%2,%3}, {%4,%5,%6,%7}, {%8,%9}, {%0,%1,%2,%3};" \
        : "+f"((d)[0]), "+f"((d)[1]), "+f"((d)[2]), "+f"((d)[3]) \
        : "r"((a)[0]), "r"((a)[1]), "r"((a)[2]), "r"((a)[3]), \
          "r"((b)[0]), "r"((b)[1]))

#define CP16(dst, src) \
    asm volatile("cp.async.cg.shared.global [%0], [%1], 16;" :: "r"(dst), "l"(src) : "memory")
#define CPCOMMIT() asm volatile("cp.async.commit_group;" ::: "memory")
#define CPWAIT0()  asm volatile("cp.async.wait_group 0;" ::: "memory")

__device__ __forceinline__ uint32_t bf2u(__nv_bfloat16 lo, __nv_bfloat16 hi) {
    union { __nv_bfloat162 b; uint32_t u; } c;
    c.b = __halves2bfloat162(lo, hi);
    return c.u;
}

// ---------------------------------------------------------------------------
// Prep kernels: fp32 -> bf16 hi/lo split (and weight transpose)
// ---------------------------------------------------------------------------
__global__ __launch_bounds__(256) void split_f32(
    const float* __restrict__ s, __nv_bfloat16* __restrict__ hi,
    __nv_bfloat16* __restrict__ lo, int n4)
{
    int i = blockIdx.x * 256 + threadIdx.x;
    if (i >= n4) return;
    float4 v = ((const float4*)s)[i];
    union { __nv_bfloat16 b[4]; uint2 u; } ph, pl;
    float f[4] = {v.x, v.y, v.z, v.w};
#pragma unroll
    for (int j = 0; j < 4; j++) {
        __nv_bfloat16 h = __float2bfloat16(f[j]);
        ph.b[j] = h;
        pl.b[j] = __float2bfloat16(f[j] - __bfloat162float(h));
    }
    ((uint2*)hi)[i] = ph.u;
    ((uint2*)lo)[i] = pl.u;
}

// W[K][N] -> Th/Tl[N][K]  (transpose + split)
__global__ void transpose_split(const float* __restrict__ W,
                                __nv_bfloat16* __restrict__ Th,
                                __nv_bfloat16* __restrict__ Tl, int K, int N)
{
    __shared__ float t[32][33];
    const int k0 = blockIdx.y * 32, n0 = blockIdx.x * 32;
    const int tx = threadIdx.x, ty = threadIdx.y;
    for (int j = ty; j < 32; j += 8)
        t[j][tx] = W[(size_t)(k0 + j) * N + n0 + tx];
    __syncthreads();
    for (int j = ty; j < 32; j += 8) {
        float v = t[tx][j];
        __nv_bfloat16 h = __float2bfloat16(v);
        Th[(size_t)(n0 + j) * K + k0 + tx] = h;
        Tl[(size_t)(n0 + j) * K + k0 + tx] = __float2bfloat16(v - __bfloat162float(h));
    }
}

// ---------------------------------------------------------------------------
// mma.sync GEMM, bf16 hi/lo split (3 passes), fp32 accumulate.
// cp.async 2-stage pipelined mainloop. Pass-major MMA order: same-accumulator
// MMAs are 16 apart (hides HMMA RAW latency at 2 warps/SMSP).
// C[M,N] = A[M,K] @ B[N,K]^T + bias[N]
// mode 0: plain write to C.  mode 1: write Q/K/V bf16 hi/lo (Q pre-scaled).
// ---------------------------------------------------------------------------
#define GT_SMEM (128 * 1024 + 1024)

__global__ __launch_bounds__(256, 1) void gemm_tc(
    const __nv_bfloat16* __restrict__ Ah, const __nv_bfloat16* __restrict__ Al,
    const __nv_bfloat16* __restrict__ Bh, const __nv_bfloat16* __restrict__ Bl,
    const float* __restrict__ bias, float* __restrict__ C,
    int M, int N, int K, int mode)
{
    extern __shared__ char smraw[];
    const uint32_t tile = (smem_u32(smraw) + 1023u) & ~1023u;
    // stage s at tile + s*65536: A_h 0 | A_l 16K | B_h 32K | B_l 48K

    const int tid  = threadIdx.x;
    const int wid  = tid >> 5, lane = tid & 31;
    const int wm   = wid & 1, wn = wid >> 1;        // 2 x 4 warp grid
    const int bm   = blockIdx.y << 7, bn = blockIdx.x << 7;

    uint32_t a_base[4], b_base[4];
#pragma unroll
    for (int mi = 0; mi < 4; mi++) {
        const int rowA = wm * 64 + mi * 16 + (lane & 15);
        a_base[mi] = (uint32_t)rowA * 128 + (((uint32_t)lane >> 4) << 4);
    }
    const int l15 = lane & 15;
#pragma unroll
    for (int ni = 0; ni < 4; ni++) {
        const int rowB = wn * 32 + ni * 8 + (l15 & 7);
        b_base[ni] = (uint32_t)rowB * 128 + (((uint32_t)l15 >> 3) << 4);
    }

    float d[4][4][4];
#pragma unroll
    for (int mi = 0; mi < 4; mi++)
#pragma unroll
        for (int ni = 0; ni < 4; ni++)
#pragma unroll
            for (int k = 0; k < 4; k++) d[mi][ni][k] = 0.f;

    // ---- prologue: issue chunk 0 into stage 0 ----
    {
        const uint32_t st = tile;
#pragma unroll
        for (int i = 0; i < 4; i++) {
            const int idx = tid + (i << 8);
            const int r = idx >> 3, c = idx & 7;
            const uint32_t so = SWZ((uint32_t)r * 128 + (uint32_t)c * 16);
            const size_t gA = (size_t)(bm + r) * K + c * 8;
            const size_t gB = (size_t)(bn + r) * K + c * 8;
            CP16(st + so,         Ah + gA);
            CP16(st + 16384 + so, Al + gA);
            CP16(st + 32768 + so, Bh + gB);
            CP16(st + 49152 + so, Bl + gB);
        }
        CPCOMMIT();
    }

    int stg = 0;
    for (int kc = 0; kc < K; kc += 64, stg ^= 1) {
        CPWAIT0();
        __syncthreads();

        if (kc + 64 < K) {
            const uint32_t st = tile + (uint32_t)(stg ^ 1) * 65536u;
#pragma unroll
            for (int i = 0; i < 4; i++) {
                const int idx = tid + (i << 8);
                const int r = idx >> 3, c = idx & 7;
                const uint32_t so = SWZ((uint32_t)r * 128 + (uint32_t)c * 16);
                const size_t gA = (size_t)(bm + r) * K + kc + 64 + c * 8;
                const size_t gB = (size_t)(bn + r) * K + kc + 64 + c * 8;
                CP16(st + so,         Ah + gA);
                CP16(st + 16384 + so, Al + gA);
                CP16(st + 32768 + so, Bh + gB);
                CP16(st + 49152 + so, Bl + gB);
            }
            CPCOMMIT();
        }

        const uint32_t sA_h = tile + (uint32_t)stg * 65536u;
        const uint32_t sA_l = sA_h + 16384, sB_h = sA_h + 32768, sB_l = sA_h + 49152;

#pragma unroll
        for (int ks = 0; ks < 4; ks++) {
            const uint32_t kb = (uint32_t)ks << 5;
            uint32_t fAh[4][4], fAl[4][4], fBh[4][2], fBl[4][2];
#pragma unroll
            for (int mi = 0; mi < 4; mi++) {
                LDSM_X4(fAh[mi], sA_h + SWZ(a_base[mi] + kb));
                LDSM_X4(fAl[mi], sA_l + SWZ(a_base[mi] + kb));
            }
#pragma unroll
            for (int ni = 0; ni < 4; ni++) {
                LDSM_X2(fBh[ni], sB_h + SWZ(b_base[ni] + kb));
                LDSM_X2(fBl[ni], sB_l + SWZ(b_base[ni] + kb));
            }
            // pass-major: same-accumulator MMAs are 16 apart
#pragma unroll
            for (int pass = 0; pass < 3; pass++)
#pragma unroll
                for (int mi = 0; mi < 4; mi++)
#pragma unroll
                    for (int ni = 0; ni < 4; ni++) {
                        if (pass == 0)      MMA16816(d[mi][ni], fAh[mi], fBh[ni]);
                        else if (pass == 1) MMA16816(d[mi][ni], fAh[mi], fBl[ni]);
                        else                MMA16816(d[mi][ni], fAl[mi], fBh[ni]);
                    }
        }
    }

    // ---- epilogue ----
    const int q = lane >> 2;
    const int cpair = (lane & 3) << 1;
#pragma unroll
    for (int ni = 0; ni < 4; ni++) {
        const int n = bn + wn * 32 + ni * 8 + cpair;
        const float2 bs = *(const float2*)(bias + n);
#pragma unroll
        for (int mi = 0; mi < 4; mi++) {
#pragma unroll
            for (int hh = 0; hh < 2; hh++) {
                const int m = bm + wm * 64 + mi * 16 + q + hh * 8;
                float2 v;
                v.x = d[mi][ni][hh * 2 + 0] + bs.x;
                v.y = d[mi][ni][hh * 2 + 1] + bs.y;
                if (mode == 1) {
                    const int cc = n >> 10, hd = (n >> 6) & 15, dd = n & 63;
                    const int bb = m >> 11, ss = m & 2047;
                    const float sc = (cc == 0) ? 0.125f : 1.0f;
                    const float vx = v.x * sc, vy = v.y * sc;
                    const __nv_bfloat16 hx = __float2bfloat16(vx);
                    const __nv_bfloat16 hy = __float2bfloat16(vy);
                    const __nv_bfloat16 lx = __float2bfloat16(vx - __bfloat162float(hx));
                    const __nv_bfloat16 ly = __float2bfloat16(vy - __bfloat162float(hy));
                    const size_t off = ((size_t)(bb * HEADS + hd) * SEQ + ss) * DH + dd;
                    __nv_bfloat16* dh = (cc == 0) ? g_q_h : (cc == 1) ? g_k_h : g_v_h;
                    __nv_bfloat16* dl = (cc == 0) ? g_q_l : (cc == 1) ? g_k_l : g_v_l;
                    *(uint32_t*)(dh + off) = bf2u(hx, hy);
                    *(uint32_t*)(dl + off) = bf2u(lx, ly);
                } else {
                    *(float2*)(C + (size_t)m * N + n) = v;
                }
            }
        }
    }
}

// ---------------------------------------------------------------------------
// Tensor-core flash attention: 128 threads / 4 warps, 128 q-rows per CTA,
// 2 CTAs/SM. 64-key tiles, cp.async double-buffered. QK^T and PV 3-pass
// bf16 hi/lo split. Pass-major MMA order (same-acc spacing 16) with
// fragment preloading for ILP.
// ---------------------------------------------------------------------------
#define AT_SMEM (96 * 1024 + 1024)

__global__ __launch_bounds__(128, 2) void attn_mma()
{
    extern __shared__ char smraw[];
    const uint32_t base = (smem_u32(smraw) + 1023u) & ~1023u;
    const uint32_t sQh = base, sQl = base + 16384;
    const uint32_t sStage = base + 32768;  // + s*32768: Kh 0 | Kl 8K | Vh 16K | Vl 24K

    const int tid = threadIdx.x, lane = tid & 31, wid = tid >> 5;
    const int bh = blockIdx.y;
    const int q0 = blockIdx.x << 7;
    const size_t hbase = (size_t)bh * (SEQ * DH);

    // ---- prologue: cp.async key-tile 0 ----
    {
        const uint32_t st = sStage;
#pragma unroll
        for (int j = 0; j < 4; j++) {
            const int idx = tid + (j << 7);        // 0..511
            const int r = idx >> 3, c = idx & 7;
            const uint32_t so = SWZ((uint32_t)r * 128 + (uint32_t)c * 16);
            const size_t g = hbase + (size_t)r * DH + c * 8;
            CP16(st + so,         g_k_h + g);
            CP16(st + 8192 + so,  g_k_l + g);
            CP16(st + 16384 + so, g_v_h + g);
            CP16(st + 24576 + so, g_v_l + g);
        }
        CPCOMMIT();
    }
    // stage Q (one-time)
    for (int i = tid; i < 1024; i += 128) {
        const int r = i >> 3, c = i & 7;
        const uint32_t so = SWZ((uint32_t)r * 128 + (uint32_t)c * 16);
        const size_t g = hbase + (size_t)(q0 + r) * DH + c * 8;
        uint4 v;
        v = *(const uint4*)(g_q_h + g); STS128(sQh + so, v);
        v = *(const uint4*)(g_q_l + g); STS128(sQl + so, v);
    }
    __syncthreads();

    // Q fragments (persistent): 2 m-frags x 4 k-steps, hi & lo
    uint32_t qh[2][4][4], ql[2][4][4];
#pragma unroll
    for (int mi = 0; mi < 2; mi++) {
        const uint32_t qoff =
            (uint32_t)(wid * 32 + mi * 16 + (lane & 15)) * 128 + ((lane >> 4) << 4);
#pragma unroll
        for (int ks = 0; ks < 4; ks++) {
            LDSM_X4(qh[mi][ks], sQh + SWZ(qoff + ks * 32));
            LDSM_X4(ql[mi][ks], sQl + SWZ(qoff + ks * 32));
        }
    }

    float O[2][8][4];
#pragma unroll
    for (int mi = 0; mi < 2; mi++)
#pragma unroll
        for (int nt = 0; nt < 8; nt++)
#pragma unroll
            for (int e = 0; e < 4; e++) O[mi][nt][e] = 0.f;
    float m_i[2][2], l_i[2][2];
#pragma unroll
    for (int mi = 0; mi < 2; mi++) {
        m_i[mi][0] = m_i[mi][1] = -3.0e38f;
        l_i[mi][0] = l_i[mi][1] = 0.f;
    }

    const int krow = (lane & 7) + ((lane >> 4) << 3);
    const uint32_t kchunk = ((uint32_t)(lane >> 3) & 1) << 4;
    const int vrow_l = lane & 15;
    const uint32_t vchunk = ((uint32_t)lane >> 4) << 4;

    for (int kt = 0; kt < SEQ / 64; kt++) {
        CPWAIT0();
        __syncthreads();

        if (kt + 1 < SEQ / 64) {
            const size_t rb = hbase + (size_t)((kt + 1) << 6) * DH;
            const uint32_t st = sStage + ((kt + 1) & 1) * 32768;
#pragma unroll
            for (int j = 0; j < 4; j++) {
                const int idx = tid + (j << 7);
                const int r = idx >> 3, c = idx & 7;
                const uint32_t so = SWZ((uint32_t)r * 128 + (uint32_t)c * 16);
                const size_t g = rb + (size_t)r * DH + c * 8;
                CP16(st + so,         g_k_h + g);
                CP16(st + 8192 + so,  g_k_l + g);
                CP16(st + 16384 + so, g_v_h + g);
                CP16(st + 24576 + so, g_v_l + g);
            }
            CPCOMMIT();
        }

        const uint32_t stK_h = sStage + (kt & 1) * 32768;
        const uint32_t stK_l = stK_h + 8192;
        const uint32_t stV_h = stK_h + 16384;
        const uint32_t stV_l = stK_h + 24576;

        // ---- S = Qhi*Khi + Qhi*Klo + Qlo*Khi ----
        float S[2][8][4];
#pragma unroll
        for (int mi = 0; mi < 2; mi++)
#pragma unroll
            for (int nt = 0; nt < 8; nt++)
#pragma unroll
                for (int e = 0; e < 4; e++) S[mi][nt][e] = 0.f;

#pragma unroll
        for (int ks = 0; ks < 4; ks++) {
            uint32_t kbh[4][4], kbl[4][4];
#pragma unroll
            for (int g = 0; g < 4; g++) {
                const uint32_t off = SWZ((uint32_t)(g * 16 + krow) * 128 + (ks << 5) + kchunk);
                LDSM_X4(kbh[g], stK_h + off);
                LDSM_X4(kbl[g], stK_l + off);
            }
            // pass-major: same-accumulator MMAs are 16 apart
#pragma unroll
            for (int pass = 0; pass < 3; pass++)
#pragma unroll
                for (int g = 0; g < 4; g++)
#pragma unroll
                    for (int mi = 0; mi < 2; mi++) {
                        const uint32_t* a = (pass == 2) ? ql[mi][ks] : qh[mi][ks];
                        const uint32_t* b = (pass == 1) ? kbl[g] : kbh[g];
                        MMA16816(S[mi][2 * g],     a, &b[0]);
                        MMA16816(S[mi][2 * g + 1], a, &b[2]);
                    }
        }

        // ---- online softmax per m-frag ----
#pragma unroll
        for (int mi = 0; mi < 2; mi++) {
            float rx0 = -3.0e38f, rx1 = -3.0e38f;
#pragma unroll
            for (int nt = 0; nt < 8; nt++) {
                rx0 = fmaxf(rx0, fmaxf(S[mi][nt][0], S[mi][nt][1]));
                rx1 = fmaxf(rx1, fmaxf(S[mi][nt][2], S[mi][nt][3]));
            }
            rx0 = fmaxf(rx0, __shfl_xor_sync(0xffffffffu, rx0, 1));
            rx0 = fmaxf(rx0, __shfl_xor_sync(0xffffffffu, rx0, 2));
            rx1 = fmaxf(rx1, __shfl_xor_sync(0xffffffffu, rx1, 1));
            rx1 = fmaxf(rx1, __shfl_xor_sync(0xffffffffu, rx1, 2));
            const float mn0 = fmaxf(m_i[mi][0], rx0), mn1 = fmaxf(m_i[mi][1], rx1);
            const float a0 = __expf(m_i[mi][0] - mn0), a1 = __expf(m_i[mi][1] - mn1);
            float s0 = 0.f, s1 = 0.f;
#pragma unroll
            for (int nt = 0; nt < 8; nt++) {
                S[mi][nt][0] = __expf(S[mi][nt][0] - mn0);
                S[mi][nt][1] = __expf(S[mi][nt][1] - mn0);
                S[mi][nt][2] = __expf(S[mi][nt][2] - mn1);
                S[mi][nt][3] = __expf(S[mi][nt][3] - mn1);
                s0 += S[mi][nt][0] + S[mi][nt][1];
                s1 += S[mi][nt][2] + S[mi][nt][3];
            }
            s0 += __shfl_xor_sync(0xffffffffu, s0, 1);
            s0 += __shfl_xor_sync(0xffffffffu, s0, 2);
            s1 += __shfl_xor_sync(0xffffffffu, s1, 1);
            s1 += __shfl_xor_sync(0xffffffffu, s1, 2);
            l_i[mi][0] = l_i[mi][0] * a0 + s0;
            l_i[mi][1] = l_i[mi][1] * a1 + s1;
            m_i[mi][0] = mn0; m_i[mi][1] = mn1;
#pragma unroll
            for (int nt = 0; nt < 8; nt++) {
                O[mi][nt][0] *= a0; O[mi][nt][1] *= a0;
                O[mi][nt][2] *= a1; O[mi][nt][3] *= a1;
            }
        }

        // ---- PV: O += Ph*Vh + Pl*Vh + Ph*Vl (V^T via ldmatrix.trans) ----
#pragma unroll
        for (int c = 0; c < 4; c++) {
            uint32_t ph[2][4], pl[2][4];
#pragma unroll
            for (int mi = 0; mi < 2; mi++)
#pragma unroll
                for (int j = 0; j < 4; j++) {
                    const int nt = 2 * c + (j >> 1);
                    const int e0 = (j & 1) * 2;
                    const float p0 = S[mi][nt][e0], p1 = S[mi][nt][e0 + 1];
                    const __nv_bfloat16 b0 = __float2bfloat16(p0);
                    const __nv_bfloat16 b1 = __float2bfloat16(p1);
                    ph[mi][j] = bf2u(b0, b1);
                    pl[mi][j] = bf2u(__float2bfloat16(p0 - __bfloat162float(b0)),
                                     __float2bfloat16(p1 - __bfloat162float(b1)));
                }
            uint32_t vbh[4][4], vbl[4][4];
#pragma unroll
            for (int g = 0; g < 4; g++) {
                const uint32_t off =
                    SWZ((uint32_t)(c * 16 + vrow_l) * 128 + ((uint32_t)g << 5) + vchunk);
                LDSM_X4T(vbh[g], stV_h + off);
                LDSM_X4T(vbl[g], stV_l + off);
            }
            // pass-major: same-accumulator MMAs are 16 apart
#pragma unroll
            for (int pass = 0; pass < 3; pass++)
#pragma unroll
                for (int g = 0; g < 4; g++)
#pragma unroll
                    for (int mi = 0; mi < 2; mi++) {
                        const uint32_t* a = (pass == 1) ? pl[mi] : ph[mi];
                        const uint32_t* b = (pass == 2) ? vbl[g] : vbh[g];
                        MMA16816(O[mi][2 * g],     a, &b[0]);
                        MMA16816(O[mi][2 * g + 1], a, &b[2]);
                    }
        }
    }

    // ---- finalize: O/l -> bf16 hi/lo -> g_attn [b][s][h*64+d] ----
    const int b_ = bh >> 4, h_ = bh & 15;
#pragma unroll
    for (int mi = 0; mi < 2; mi++) {
        const float inv0 = 1.0f / l_i[mi][0], inv1 = 1.0f / l_i[mi][1];
        const int row0 = q0 + wid * 32 + mi * 16 + (lane >> 2);
#pragma unroll
        for (int nt = 0; nt < 8; nt++) {
            const int dcol = nt * 8 + ((lane & 3) << 1);
#pragma unroll
            for (int hh = 0; hh < 2; hh++) {
                const int row = row0 + hh * 8;
                const float inv = hh ? inv1 : inv0;
                const float v0 = O[mi][nt][hh * 2 + 0] * inv;
                const float v1 = O[mi][nt][hh * 2 + 1] * inv;
                const __nv_bfloat16 h0 = __float2bfloat16(v0);
                const __nv_bfloat16 h1 = __float2bfloat16(v1);
                const size_t off = ((size_t)b_ * SEQ + row) * HID + h_ * DH + dcol;
                *(uint32_t*)(g_attn_h + off) = bf2u(h0, h1);
                *(uint32_t*)(g_attn_l + off) =
                    bf2u(__float2bfloat16(v0 - __bfloat162float(h0)),
                         __float2bfloat16(v1 - __bfloat162float(h1)));
            }
        }
    }
}

// ---------------------------------------------------------------------------
extern "C" void kernel_launch(void* const* d_in, const int* in_sizes, int n_in,
                              void* d_out, int out_size)
{
    const float* x    = (const float*)d_in[0];
    const float* Wqkv = (const float*)d_in[1];
    const float* bqkv = (const float*)d_in[2];
    const float* Wout = (const float*)d_in[3];
    const float* bout = (const float*)d_in[4];
    float* out = (float*)d_out;

    cudaFuncSetAttribute(gemm_tc,
                         cudaFuncAttributeMaxDynamicSharedMemorySize, GT_SMEM);
    cudaFuncSetAttribute(attn_mma,
                         cudaFuncAttributeMaxDynamicSharedMemorySize, AT_SMEM);

    __nv_bfloat16 *xh, *xl, *wqh, *wql, *woh, *wol, *ath, *atl;
    cudaGetSymbolAddress((void**)&xh,  g_x_h);
    cudaGetSymbolAddress((void**)&xl,  g_x_l);
    cudaGetSymbolAddress((void**)&wqh, g_wq_h);
    cudaGetSymbolAddress((void**)&wql, g_wq_l);
    cudaGetSymbolAddress((void**)&woh, g_wo_h);
    cudaGetSymbolAddress((void**)&wol, g_wo_l);
    cudaGetSymbolAddress((void**)&ath, g_attn_h);
    cudaGetSymbolAddress((void**)&atl, g_attn_l);

    // 0) prep: split x; transpose+split weights
    split_f32<<<(MTOT * HID / 4 + 255) / 256, 256>>>(x, xh, xl, MTOT * HID / 4);
    transpose_split<<<dim3(3 * HID / 32, HID / 32), dim3(32, 8)>>>(Wqkv, wqh, wql, HID, 3 * HID);
    transpose_split<<<dim3(HID / 32, HID / 32), dim3(32, 8)>>>(Wout, woh, wol, HID, HID);

    // 1) QKV projection -> Q/K/V bf16 hi/lo (Q pre-scaled by 1/8)
    gemm_tc<<<dim3(3 * HID / 128, MTOT / 128), 256, GT_SMEM>>>(
        xh, xl, wqh, wql, bqkv, nullptr, MTOT, 3 * HID, HID, 1);

    // 2) Tensor-core flash attention -> g_attn_h/l
    attn_mma<<<dim3(SEQ / 128, NBH), 128, AT_SMEM>>>();

    // 3) Output projection + bias -> out
    gemm_tc<<<dim3(HID / 128, MTOT / 128), 256, GT_SMEM>>>(
        ath, atl, woh, wol, bout, out, MTOT, HID, HID, 0);
}